// round 12
// baseline (speedup 1.0000x reference)
#include <cuda_runtime.h>
#include <cuda_bf16.h>
#include <cstdint>
#include <cstddef>

#define NN 100000
#define EE 1600000
#define FF 128
#define HH 128
#define LL 4
#define SS 10000
#define GG 256
#define CC 10
#define SCAN_NB 98
#define NTILES 782
#define MMGRID 148

// ---------------- scratch (device globals; no allocation allowed) ----------------
__device__ int   d_deg[NN];
__device__ int   d_off[NN + 1];
__device__ int   d_cursor[NN];
__device__ int   d_csr[EE];
__device__ int   d_bsum[SCAN_NB];
__device__ __nv_bfloat16 d_ubf[(size_t)NN * HH];
__device__ __nv_bfloat16 d_tbf[(size_t)NN * HH];
__device__ __nv_bfloat16 d_xbf[(size_t)NN * FF];
__device__ __nv_bfloat16 d_featbf[(size_t)NN * LL * HH];
__device__ float d_statsA[8 * 256];
__device__ int   d_suboff[SS + 1];
__device__ int   d_gphoff[GG + 1];
__device__ float d_sub[(size_t)SS * LL * HH];
__device__ float d_gph[(size_t)GG * LL * HH];
__device__ __nv_bfloat16 d_Wbf[8 * 128 * 128];

// ---------------- smem layout for persistent mm kernel ----------------
#define SM_BIAS  0
#define SM_SSC   512
#define SM_SSH   1024
#define SM_STATS 1536
#define SM_WH    2560
#define SM_STG0  (SM_WH + 34816)      // 37376
#define STGB     34816                // 128 rows * 272B (bf16 stage)
#define SM_STG1  (SM_STG0 + STGB)     // 72192
#define MM_SMEM  (SM_STG1 + STGB)     // 107008

__device__ __forceinline__ uint32_t smem_u32(const void* p) {
    uint32_t a;
    asm("{ .reg .u64 t; cvta.to.shared.u64 t, %1; cvt.u32.u64 %0, t; }" : "=r"(a) : "l"(p));
    return a;
}
__device__ __forceinline__ void ldsm_x2(uint32_t* b, uint32_t addr) {
    asm volatile("ldmatrix.sync.aligned.m8n8.x2.shared.b16 {%0,%1}, [%2];"
        : "=r"(b[0]), "=r"(b[1]) : "r"(addr));
}
__device__ __forceinline__ void mma_bf16(float* c, const uint32_t* a, const uint32_t* b) {
    asm volatile("mma.sync.aligned.m16n8k16.row.col.f32.bf16.bf16.f32 "
        "{%0,%1,%2,%3}, {%4,%5,%6,%7}, {%8,%9}, {%0,%1,%2,%3};"
        : "+f"(c[0]), "+f"(c[1]), "+f"(c[2]), "+f"(c[3])
        : "r"(a[0]), "r"(a[1]), "r"(a[2]), "r"(a[3]), "r"(b[0]), "r"(b[1]));
}
__device__ __forceinline__ void cpasync16(uint32_t dst, const void* src, int sz) {
    asm volatile("cp.async.ca.shared.global [%0], [%1], 16, %2;"
        :: "r"(dst), "l"(src), "r"(sz) : "memory");
}
#define CP_COMMIT() asm volatile("cp.async.commit_group;" ::: "memory")
#define CP_WAIT0()  asm volatile("cp.async.wait_group 0;" ::: "memory")

__device__ __forceinline__ uint32_t pack_bf2(float2 v) {
    __nv_bfloat162 h = __floats2bfloat162_rn(v.x, v.y);
    return *reinterpret_cast<uint32_t*>(&h);
}
__device__ __forceinline__ float2 unpack_bf2(uint32_t w) {
    return make_float2(__uint_as_float(w << 16), __uint_as_float(w & 0xFFFF0000u));
}
__device__ __forceinline__ float4 bf4_to_f4(uint2 w) {
    float2 f0 = unpack_bf2(w.x);
    float2 f1 = unpack_bf2(w.y);
    return make_float4(f0.x, f0.y, f1.x, f1.y);
}
__device__ __forceinline__ uint32_t act_bf2(uint32_t w, float2 sc, float2 sh) {
    float2 v = unpack_bf2(w);
    v.x = fmaxf(fmaf(v.x, sc.x, sh.x), 0.f);
    v.y = fmaxf(fmaf(v.y, sc.y, sh.y), 0.f);
    return pack_bf2(v);
}

template <bool HAS_T>
__device__ __forceinline__ float4 act4(float4 v, float4 sc, float4 sh) {
    if (HAS_T) {
        v.x = fmaxf(fmaf(v.x, sc.x, sh.x), 0.f);
        v.y = fmaxf(fmaf(v.y, sc.y, sh.y), 0.f);
        v.z = fmaxf(fmaf(v.z, sc.z, sh.z), 0.f);
        v.w = fmaxf(fmaf(v.w, sc.w, sh.w), 0.f);
    }
    return v;
}

__device__ __forceinline__ void bn_from_stats(const float* st, const float* gamma,
                                              const float* beta, int c,
                                              float& sc, float& sh) {
    const float inv_n = 1.0f / (float)NN;
    float mu = st[c] * inv_n;
    float var = fmaf(-mu, mu, st[HH + c] * inv_n);
    float rinv = rsqrtf(var + 1e-5f);
    sc = rinv * gamma[c];
    sh = fmaf(-mu, sc, beta[c]);
}

__device__ __forceinline__ void mm_issue_copy(const __nv_bfloat16* __restrict__ Ain, int lda,
                                              uint32_t sb, int tile, int buf, int tid) {
    uint32_t base = sb + SM_STG0 + (uint32_t)buf * STGB;
    int row0 = tile * 128;
#pragma unroll
    for (int j = 0; j < 8; j++) {
        int c = tid + 256 * j;
        int r = c >> 4, ch = c & 15;
        int gr = row0 + r;
        uint32_t dst = base + (uint32_t)(r * 272 + ch * 16);
        int ok = (gr < NN) ? 16 : 0;
        const __nv_bfloat16* src = Ain + (size_t)(gr < NN ? gr : 0) * lda + ch * 8;
        cpasync16(dst, src, ok);
    }
}

// ---------------- init: x -> bf16 convert + zero deg/stats ----------------
__global__ void init_kernel(const float* __restrict__ x) {
    int i = blockIdx.x * blockDim.x + threadIdx.x;
    if (i < NN * 32) {
        float4 v = *(const float4*)&x[(size_t)i * 4];
        uint2 o;
        o.x = pack_bf2(make_float2(v.x, v.y));
        o.y = pack_bf2(make_float2(v.z, v.w));
        *(uint2*)&d_xbf[(size_t)i * 4] = o;
    }
    if (i < NN) d_deg[i] = 0;
    if (i < 8 * 256) d_statsA[i] = 0.f;
}

// ---------------- aggregation: 2 nodes/warp, masked double-buffered batches ----------------
#define AGG_ISSUE(W, JB) do { \
    _Pragma("unroll") \
    for (int q = 0; q < 8; q++) { \
        int jj = (JB) + q; \
        int idx = (jj < epos) ? d_csr[jj] : node; \
        (W)[q] = *(const uint4*)&xin[(size_t)idx * ldx + c0]; \
    } \
} while (0)

#define AGG_CONSUME(W, JB) do { \
    _Pragma("unroll") \
    for (int q = 0; q < 8; q++) { \
        float mq = ((JB) + q < epos) ? 1.f : 0.f; \
        const uint32_t* ww = (const uint32_t*)&(W)[q]; \
        _Pragma("unroll") \
        for (int k = 0; k < 4; k++) { \
            float2 v = unpack_bf2(ww[k]); \
            if (HAS_T) { \
                v.x = fmaxf(fmaf(v.x, sc[2 * k], sh[2 * k]), 0.f); \
                v.y = fmaxf(fmaf(v.y, sc[2 * k + 1], sh[2 * k + 1]), 0.f); \
            } \
            acc[2 * k]     = fmaf(mq, v.x, acc[2 * k]); \
            acc[2 * k + 1] = fmaf(mq, v.y, acc[2 * k + 1]); \
        } \
    } \
} while (0)

template <bool HAS_T>
__global__ void agg_kernel(const __nv_bfloat16* __restrict__ xin, int ldx,
                           const float* __restrict__ stats_in,
                           const float* __restrict__ gamma, const float* __restrict__ beta,
                           const float* __restrict__ eps_ptr, int layer,
                           __nv_bfloat16* __restrict__ u) {
    __shared__ float ssc[HH], ssh[HH];
    int tid = threadIdx.x;
    if (HAS_T) {
        if (tid < HH) bn_from_stats(stats_in, gamma, beta, tid, ssc[tid], ssh[tid]);
        __syncthreads();
    }
    int wid = tid >> 5, lane = tid & 31;
    int half = lane >> 4, hl = lane & 15;
    int node = blockIdx.x * 16 + wid * 2 + half;
    if (node >= NN) return;
    float e = 1.0f + eps_ptr[layer];
    int c0 = hl * 8;
    float sc[8], sh[8];
    if (HAS_T) {
#pragma unroll
        for (int q = 0; q < 8; q++) { sc[q] = ssc[c0 + q]; sh[q] = ssh[c0 + q]; }
    }
    int s = d_off[node], epos = d_off[node + 1];
    float acc[8];
#pragma unroll
    for (int q = 0; q < 8; q++) acc[q] = 0.f;

    uint4 wA[8], wB[8];
    int jb = s;
    if (jb < epos) {
        AGG_ISSUE(wA, jb);
#pragma unroll 1
        while (true) {
            int nb = jb + 8;
            if (nb < epos) AGG_ISSUE(wB, nb);
            AGG_CONSUME(wA, jb);
            jb = nb;
            if (jb >= epos) break;
            nb = jb + 8;
            if (nb < epos) AGG_ISSUE(wA, nb);
            AGG_CONSUME(wB, jb);
            jb = nb;
            if (jb >= epos) break;
        }
    }
    // self term
    {
        uint4 w0 = *(const uint4*)&xin[(size_t)node * ldx + c0];
        const uint32_t* ww = (const uint32_t*)&w0;
#pragma unroll
        for (int k = 0; k < 4; k++) {
            float2 v = unpack_bf2(ww[k]);
            if (HAS_T) {
                v.x = fmaxf(fmaf(v.x, sc[2 * k], sh[2 * k]), 0.f);
                v.y = fmaxf(fmaf(v.y, sc[2 * k + 1], sh[2 * k + 1]), 0.f);
            }
            acc[2 * k] = fmaf(e, v.x, acc[2 * k]);
            acc[2 * k + 1] = fmaf(e, v.y, acc[2 * k + 1]);
        }
    }
    uint4 o;
    uint32_t* oo = (uint32_t*)&o;
#pragma unroll
    for (int k = 0; k < 4; k++)
        oo[k] = pack_bf2(make_float2(acc[2 * k], acc[2 * k + 1]));
    *(uint4*)&u[(size_t)node * HH + c0] = o;
}

// ---------------- persistent pipelined GEMM: Y = act(Ain) @ W^T + bias ----------------
template <bool HAS_T>
__global__ void __launch_bounds__(256, 1)
mm_hmma_kernel(const __nv_bfloat16* __restrict__ Ain, int lda,
               const float* __restrict__ stats_in,
               const float* __restrict__ gamma, const float* __restrict__ beta,
               const __nv_bfloat16* __restrict__ Wbf,
               const float* __restrict__ bias,
               float* __restrict__ stats_out,
               __nv_bfloat16* __restrict__ Y, int ldy) {
    extern __shared__ char smem[];
    uint32_t sb = smem_u32(smem);
    int tid = threadIdx.x, wid = tid >> 5, lane = tid & 31;
    int gid = lane >> 2, ctib = lane & 3;
    float* sbias = (float*)(smem + SM_BIAS);
    float* ssc   = (float*)(smem + SM_SSC);
    float* ssh   = (float*)(smem + SM_SSH);
    float* sstat = (float*)(smem + SM_STATS);

    if (tid < 128) {
        sbias[tid] = bias[tid];
        if (HAS_T) bn_from_stats(stats_in, gamma, beta, tid, ssc[tid], ssh[tid]);
    }
    sstat[tid] = 0.f;

#pragma unroll
    for (int i = tid; i < 128 * 16; i += 256) {
        int r = i >> 4, c8 = (i & 15) * 8;
        uint32_t dsto = (uint32_t)(r * 272 + c8 * 2);
        *(uint4*)(smem + SM_WH + dsto) = *(const uint4*)&Wbf[r * 128 + c8];
    }

    mm_issue_copy(Ain, lda, sb, blockIdx.x, 0, tid);
    CP_COMMIT();

    float sA[16], sB[16], qA[16], qB[16];
#pragma unroll
    for (int nt = 0; nt < 16; nt++) { sA[nt] = 0.f; sB[nt] = 0.f; qA[nt] = 0.f; qB[nt] = 0.f; }

    int p = 0;
    int r0w = 16 * wid + gid;
#pragma unroll 1
    for (int tile = blockIdx.x; tile < NTILES; tile += MMGRID) {
        CP_WAIT0();
        __syncthreads();

        // issue next tile's copy first (into the other buffer) to overlap with fragment build
        int nxt = tile + MMGRID;
        if (nxt < NTILES) mm_issue_copy(Ain, lda, sb, nxt, 1 - p, tid);
        CP_COMMIT();

        const char* stg = smem + SM_STG0 + (uint32_t)p * STGB;
        uint32_t ah[32];
#pragma unroll
        for (int k8 = 0; k8 < 8; k8++) {
            uint32_t co = (uint32_t)(k8 * 32 + ctib * 4);
            uint32_t w00 = *(const uint32_t*)(stg + r0w * 272 + co);
            uint32_t w10 = *(const uint32_t*)(stg + (r0w + 8) * 272 + co);
            uint32_t w01 = *(const uint32_t*)(stg + r0w * 272 + co + 16);
            uint32_t w11 = *(const uint32_t*)(stg + (r0w + 8) * 272 + co + 16);
            if (HAS_T) {
                int cc = k8 * 16 + 2 * ctib;
                float2 sa = *(const float2*)&ssc[cc],     ha = *(const float2*)&ssh[cc];
                float2 sc = *(const float2*)&ssc[cc + 8], hc = *(const float2*)&ssh[cc + 8];
                w00 = act_bf2(w00, sa, ha);
                w10 = act_bf2(w10, sa, ha);
                w01 = act_bf2(w01, sc, hc);
                w11 = act_bf2(w11, sc, hc);
            }
            ah[k8 * 4 + 0] = w00;
            ah[k8 * 4 + 1] = w10;
            ah[k8 * 4 + 2] = w01;
            ah[k8 * 4 + 3] = w11;
        }

        int row0 = tile * 128;
        int g = lane & 7, q = (lane >> 3) & 1;
        uint32_t wbase = sb + SM_WH + (uint32_t)(g * 272 + q * 16);
#pragma unroll
        for (int nt = 0; nt < 16; nt++) {
            float ca[4] = {0.f, 0.f, 0.f, 0.f};
            float cb[4] = {0.f, 0.f, 0.f, 0.f};
#pragma unroll
            for (int k8 = 0; k8 < 4; k8++) {
                uint32_t wa = wbase + (uint32_t)(nt * 8 * 272 + k8 * 32);
                uint32_t bh[2], bh2[2];
                ldsm_x2(bh, wa);
                ldsm_x2(bh2, wa + 4 * 32);
                mma_bf16(ca, &ah[k8 * 4], bh);
                mma_bf16(cb, &ah[(k8 + 4) * 4], bh2);
            }
            int col = nt * 8 + 2 * ctib;
            float bx = sbias[col], by = sbias[col + 1];
            float v0 = ca[0] + cb[0] + bx;
            float v1 = ca[1] + cb[1] + by;
            float v2 = ca[2] + cb[2] + bx;
            float v3 = ca[3] + cb[3] + by;
            int gr0 = row0 + r0w, gr1 = gr0 + 8;
            if (gr0 < NN)
                *(uint32_t*)&Y[(size_t)gr0 * ldy + col] = pack_bf2(make_float2(v0, v1));
            else { v0 = 0.f; v1 = 0.f; }
            if (gr1 < NN)
                *(uint32_t*)&Y[(size_t)gr1 * ldy + col] = pack_bf2(make_float2(v2, v3));
            else { v2 = 0.f; v3 = 0.f; }
            sA[nt] += v0 + v2;
            sB[nt] += v1 + v3;
            qA[nt] = fmaf(v0, v0, fmaf(v2, v2, qA[nt]));
            qB[nt] = fmaf(v1, v1, fmaf(v3, v3, qB[nt]));
        }
        p ^= 1;
    }

#pragma unroll
    for (int nt = 0; nt < 16; nt++) {
        float s0 = sA[nt], s1 = sB[nt], q0 = qA[nt], q1 = qB[nt];
#pragma unroll
        for (int h = 4; h < 32; h <<= 1) {
            s0 += __shfl_xor_sync(0xffffffffu, s0, h);
            s1 += __shfl_xor_sync(0xffffffffu, s1, h);
            q0 += __shfl_xor_sync(0xffffffffu, q0, h);
            q1 += __shfl_xor_sync(0xffffffffu, q1, h);
        }
        if (lane < 4) {
            int col = nt * 8 + 2 * lane;
            atomicAdd(&sstat[col], s0);
            atomicAdd(&sstat[col + 1], s1);
            atomicAdd(&sstat[128 + col], q0);
            atomicAdd(&sstat[128 + col + 1], q1);
        }
    }
    __syncthreads();
    atomicAdd(&stats_out[tid], sstat[tid]);
}

// ---------------- W conversion (single-term bf16) ----------------
__global__ void convw_kernel(const float* __restrict__ W1, const float* __restrict__ W2) {
    int i = blockIdx.x * 256 + threadIdx.x;
    if (i >= 8 * 16384) return;
    int mat = i >> 14, e = i & 16383, l = mat >> 1;
    float v = (mat & 1) ? W2[(size_t)l * 16384 + e] : W1[(size_t)l * 16384 + e];
    d_Wbf[i] = __float2bfloat16(v);
}

// ---------------- CSR build ----------------
__global__ void count_kernel(const int* __restrict__ dst) {
    int i = blockIdx.x * blockDim.x + threadIdx.x;
    if (i < EE) atomicAdd(&d_deg[dst[i]], 1);
}

__global__ void scan1_kernel() {
    __shared__ int wsum[32];
    int t = threadIdx.x, lane = t & 31, w = t >> 5;
    int idx = blockIdx.x * 1024 + t;
    int v = (idx < NN) ? d_deg[idx] : 0;
    int x = v;
#pragma unroll
    for (int d = 1; d < 32; d <<= 1) {
        int y = __shfl_up_sync(0xffffffffu, x, d);
        if (lane >= d) x += y;
    }
    if (lane == 31) wsum[w] = x;
    __syncthreads();
    if (w == 0) {
        int s = wsum[lane];
#pragma unroll
        for (int d = 1; d < 32; d <<= 1) {
            int y = __shfl_up_sync(0xffffffffu, s, d);
            if (lane >= d) s += y;
        }
        wsum[lane] = s;
    }
    __syncthreads();
    int woff = (w > 0) ? wsum[w - 1] : 0;
    int excl = woff + x - v;
    if (idx < NN) d_off[idx] = excl;
    if (t == 1023) d_bsum[blockIdx.x] = woff + x;
}

__global__ void scan2_kernel() {
    __shared__ int bs[SCAN_NB];
    __shared__ int boff_s;
    int t = threadIdx.x;
    if (t < SCAN_NB) bs[t] = d_bsum[t];
    __syncthreads();
    if (t == 0) {
        int acc = 0;
#pragma unroll 1
        for (int b = 0; b < (int)blockIdx.x; b++) acc += bs[b];
        boff_s = acc;
        if (blockIdx.x == SCAN_NB - 1) {
            int tot = acc;
            for (int b = blockIdx.x; b < SCAN_NB; b++) tot += bs[b];
            d_off[NN] = tot;
        }
    }
    __syncthreads();
    int boff = boff_s;
    int idx = blockIdx.x * 1024 + t;
    if (idx < NN) {
        int val = d_off[idx] + boff;
        d_off[idx] = val;
        d_cursor[idx] = val;
    }
}

__global__ void fill_kernel(const int* __restrict__ src, const int* __restrict__ dst) {
    int i = blockIdx.x * blockDim.x + threadIdx.x;
    if (i < EE) {
        int p = atomicAdd(&d_cursor[dst[i]], 1);
        d_csr[p] = src[i];
    }
}

// ---------------- pooling offsets (both levels in one launch) ----------------
__global__ void offsets_kernel(const int* __restrict__ n2s, const int* __restrict__ s2g) {
    int i = blockIdx.x * blockDim.x + threadIdx.x;
    if (i <= SS) {
        int lo = 0, hi = NN;
        while (lo < hi) {
            int mid = (lo + hi) >> 1;
            if (n2s[mid] < i) lo = mid + 1; else hi = mid;
        }
        d_suboff[i] = lo;
    }
    int g = i - (SS + 1);
    if (g >= 0 && g <= GG) {
        int lo = 0, hi = SS;
        while (lo < hi) {
            int mid = (lo + hi) >> 1;
            if (s2g[mid] < g) lo = mid + 1; else hi = mid;
        }
        d_gphoff[g] = lo;
    }
}

__global__ void segmean1_kernel(const __nv_bfloat16* __restrict__ in, const int* __restrict__ off,
                                float* __restrict__ out,
                                const float* __restrict__ statsA,
                                const float* __restrict__ g2, const float* __restrict__ be2) {
    int s = blockIdx.x, t = threadIdx.x;
    int lt = t >> 5;
    int c0 = (t & 31) * 4;
    const float* st = statsA + (size_t)(2 * lt + 1) * 256;
    float4 sc4, sh4;
    {
        float sc, sh;
        bn_from_stats(st, g2 + lt * HH, be2 + lt * HH, c0 + 0, sc, sh); sc4.x = sc; sh4.x = sh;
        bn_from_stats(st, g2 + lt * HH, be2 + lt * HH, c0 + 1, sc, sh); sc4.y = sc; sh4.y = sh;
        bn_from_stats(st, g2 + lt * HH, be2 + lt * HH, c0 + 2, sc, sh); sc4.z = sc; sh4.z = sh;
        bn_from_stats(st, g2 + lt * HH, be2 + lt * HH, c0 + 3, sc, sh); sc4.w = sc; sh4.w = sh;
    }
    int r0 = off[s], r1 = off[s + 1];
    float4 acc = make_float4(0.f, 0.f, 0.f, 0.f);
    for (int r = r0; r < r1; r++) {
        float4 v = bf4_to_f4(*(const uint2*)&in[(size_t)r * (LL * HH) + t * 4]);
        v = act4<true>(v, sc4, sh4);
        acc.x += v.x; acc.y += v.y; acc.z += v.z; acc.w += v.w;
    }
    float inv = 1.0f / fmaxf((float)(r1 - r0), 1.0f);
    float4 o = make_float4(acc.x * inv, acc.y * inv, acc.z * inv, acc.w * inv);
    *(float4*)&out[(size_t)s * (LL * HH) + t * 4] = o;
}

__global__ void segmean2_kernel(const float* __restrict__ in, const int* __restrict__ off,
                                float* __restrict__ out) {
    int s = blockIdx.x, t = threadIdx.x;
    int r0 = off[s], r1 = off[s + 1];
    float4 acc = make_float4(0.f, 0.f, 0.f, 0.f);
    for (int r = r0; r < r1; r++) {
        float4 v = *(const float4*)&in[(size_t)r * (LL * HH) + t * 4];
        acc.x += v.x; acc.y += v.y; acc.z += v.z; acc.w += v.w;
    }
    float inv = 1.0f / fmaxf((float)(r1 - r0), 1.0f);
    float4 o = make_float4(acc.x * inv, acc.y * inv, acc.z * inv, acc.w * inv);
    *(float4*)&out[(size_t)s * (LL * HH) + t * 4] = o;
}

// ---------------- head ----------------
__global__ void head_kernel(const float* __restrict__ gph,
                            const float* __restrict__ w1, const float* __restrict__ bb1,
                            const float* __restrict__ w2, const float* __restrict__ bb2,
                            float* __restrict__ out) {
    __shared__ float grow[LL * HH];
    __shared__ float hbuf[HH];
    __shared__ float obuf[CC];
    int g = blockIdx.x, t = threadIdx.x;
    for (int i = t; i < LL * HH; i += 128) grow[i] = gph[(size_t)g * (LL * HH) + i];
    __syncthreads();
    float acc = bb1[t];
#pragma unroll 8
    for (int k = 0; k < LL * HH; k++) acc = fmaf(grow[k], w1[(size_t)t * (LL * HH) + k], acc);
    hbuf[t] = fmaxf(acc, 0.f);
    __syncthreads();
    if (t < CC) {
        float a = bb2[t];
#pragma unroll 8
        for (int k = 0; k < HH; k++) a = fmaf(hbuf[k], w2[t * HH + k], a);
        obuf[t] = a;
    }
    __syncthreads();
    if (t == 0) {
        float m = obuf[0];
#pragma unroll
        for (int j = 1; j < CC; j++) m = fmaxf(m, obuf[j]);
        float se = 0.f;
#pragma unroll
        for (int j = 0; j < CC; j++) se += expf(obuf[j] - m);
        float lse = m + logf(se);
#pragma unroll
        for (int j = 0; j < CC; j++) out[g * CC + j] = obuf[j] - lse;
    }
}

// ---------------- launcher ----------------
extern "C" void kernel_launch(void* const* d_in, const int* in_sizes, int n_in,
                              void* d_out, int out_size) {
    const float* x     = (const float*)d_in[0];
    const int*   ei    = (const int*)d_in[1];
    const int*   n2s   = (const int*)d_in[2];
    const int*   s2g   = (const int*)d_in[3];
    const float* W1    = (const float*)d_in[4];
    const float* b1    = (const float*)d_in[5];
    const float* g1    = (const float*)d_in[6];
    const float* be1   = (const float*)d_in[7];
    const float* W2    = (const float*)d_in[8];
    const float* b2    = (const float*)d_in[9];
    const float* g2    = (const float*)d_in[10];
    const float* be2   = (const float*)d_in[11];
    const float* eps   = (const float*)d_in[12];
    const float* lin1W = (const float*)d_in[13];
    const float* lin1b = (const float*)d_in[14];
    const float* lin2W = (const float*)d_in[15];
    const float* lin2b = (const float*)d_in[16];
    float* out = (float*)d_out;

    void* p;
    cudaGetSymbolAddress(&p, d_ubf);    __nv_bfloat16* ubfp   = (__nv_bfloat16*)p;
    cudaGetSymbolAddress(&p, d_tbf);    __nv_bfloat16* tbfp   = (__nv_bfloat16*)p;
    cudaGetSymbolAddress(&p, d_xbf);    __nv_bfloat16* xbfp   = (__nv_bfloat16*)p;
    cudaGetSymbolAddress(&p, d_featbf); __nv_bfloat16* featp  = (__nv_bfloat16*)p;
    cudaGetSymbolAddress(&p, d_statsA); float* statsp  = (float*)p;
    cudaGetSymbolAddress(&p, d_sub);    float* subp    = (float*)p;
    cudaGetSymbolAddress(&p, d_gph);    float* gphp    = (float*)p;
    cudaGetSymbolAddress(&p, d_suboff); int* suboffp   = (int*)p;
    cudaGetSymbolAddress(&p, d_gphoff); int* gphoffp   = (int*)p;
    cudaGetSymbolAddress(&p, d_Wbf);    __nv_bfloat16* wbfp = (__nv_bfloat16*)p;

    cudaFuncSetAttribute((const void*)mm_hmma_kernel<false>,
                         cudaFuncAttributeMaxDynamicSharedMemorySize, MM_SMEM);
    cudaFuncSetAttribute((const void*)mm_hmma_kernel<true>,
                         cudaFuncAttributeMaxDynamicSharedMemorySize, MM_SMEM);

    const int* src = ei;
    const int* dst = ei + EE;

    init_kernel<<<(NN * 32 + 255) / 256, 256>>>(x);
    convw_kernel<<<(8 * 16384 + 255) / 256, 256>>>(W1, W2);

    count_kernel<<<(EE + 255) / 256, 256>>>(dst);
    scan1_kernel<<<SCAN_NB, 1024>>>();
    scan2_kernel<<<SCAN_NB, 1024>>>();
    fill_kernel<<<(EE + 255) / 256, 256>>>(src, dst);

    const int agg_blocks = (NN + 15) / 16;
    for (int l = 0; l < LL; l++) {
        const __nv_bfloat16* w1bf = wbfp + (size_t)(l * 2) * 16384;
        const __nv_bfloat16* w2bf = wbfp + (size_t)(l * 2 + 1) * 16384;
        float* st1 = statsp + (size_t)(2 * l) * 256;
        float* st2 = statsp + (size_t)(2 * l + 1) * 256;

        if (l == 0) {
            agg_kernel<false><<<agg_blocks, 256>>>(
                xbfp, FF, nullptr, nullptr, nullptr, eps, 0, ubfp);
        } else {
            agg_kernel<true><<<agg_blocks, 256>>>(
                featp + (size_t)(l - 1) * HH, LL * HH,
                statsp + (size_t)(2 * (l - 1) + 1) * 256,
                g2 + (size_t)(l - 1) * HH, be2 + (size_t)(l - 1) * HH, eps, l, ubfp);
        }

        mm_hmma_kernel<false><<<MMGRID, 256, MM_SMEM>>>(
            ubfp, HH, nullptr, nullptr, nullptr, w1bf,
            b1 + (size_t)l * HH, st1, tbfp, HH);

        mm_hmma_kernel<true><<<MMGRID, 256, MM_SMEM>>>(
            tbfp, HH, st1, g1 + (size_t)l * HH, be1 + (size_t)l * HH,
            w2bf, b2 + (size_t)l * HH, st2,
            featp + (size_t)l * HH, LL * HH);
    }

    offsets_kernel<<<(SS + GG + 2 + 255) / 256, 256>>>(n2s, s2g);
    segmean1_kernel<<<SS, 128>>>(featp, suboffp, subp, statsp, g2, be2);
    segmean2_kernel<<<GG, 128>>>(subp, gphoffp, gphp);

    head_kernel<<<GG, 128>>>(gphp, lin1W, lin1b, lin2W, lin2b, out);
}

// round 13
// speedup vs baseline: 1.0775x; 1.0775x over previous
#include <cuda_runtime.h>
#include <cuda_bf16.h>
#include <cstdint>
#include <cstddef>

#define NN 100000
#define EE 1600000
#define FF 128
#define HH 128
#define LL 4
#define SS 10000
#define GG 256
#define CC 10
#define SCAN_NB 98
#define NTILES 782
#define MMGRID 148

// ---------------- scratch (device globals; no allocation allowed) ----------------
__device__ int   d_deg[NN];
__device__ int   d_off[NN + 1];
__device__ int   d_cursor[NN];
__device__ int   d_csr[EE];
__device__ int   d_bsum[SCAN_NB];
__device__ __nv_bfloat16 d_ubf[(size_t)NN * HH];
__device__ __nv_bfloat16 d_tbf[(size_t)NN * HH];
__device__ __nv_bfloat16 d_xbf[(size_t)NN * FF];
__device__ __nv_bfloat16 d_featbf[(size_t)NN * LL * HH];
__device__ float d_statsA[8 * 256];
__device__ int   d_suboff[SS + 1];
__device__ int   d_gphoff[GG + 1];
__device__ float d_sub[(size_t)SS * LL * HH];
__device__ float d_gph[(size_t)GG * LL * HH];
__device__ __nv_bfloat16 d_Wbf[8 * 128 * 128];

// ---------------- smem layout for persistent mm kernel ----------------
#define SM_BIAS  0
#define SM_SSC   512
#define SM_SSH   1024
#define SM_STATS 1536
#define SM_WH    2560
#define SM_STG0  (SM_WH + 34816)      // 37376
#define STGB     34816                // 128 rows * 272B (bf16 stage)
#define SM_STG1  (SM_STG0 + STGB)     // 72192
#define MM_SMEM  (SM_STG1 + STGB)     // 107008

__device__ __forceinline__ uint32_t smem_u32(const void* p) {
    uint32_t a;
    asm("{ .reg .u64 t; cvta.to.shared.u64 t, %1; cvt.u32.u64 %0, t; }" : "=r"(a) : "l"(p));
    return a;
}
__device__ __forceinline__ void ldsm_x2(uint32_t* b, uint32_t addr) {
    asm volatile("ldmatrix.sync.aligned.m8n8.x2.shared.b16 {%0,%1}, [%2];"
        : "=r"(b[0]), "=r"(b[1]) : "r"(addr));
}
__device__ __forceinline__ void mma_bf16(float* c, const uint32_t* a, const uint32_t* b) {
    asm volatile("mma.sync.aligned.m16n8k16.row.col.f32.bf16.bf16.f32 "
        "{%0,%1,%2,%3}, {%4,%5,%6,%7}, {%8,%9}, {%0,%1,%2,%3};"
        : "+f"(c[0]), "+f"(c[1]), "+f"(c[2]), "+f"(c[3])
        : "r"(a[0]), "r"(a[1]), "r"(a[2]), "r"(a[3]), "r"(b[0]), "r"(b[1]));
}
__device__ __forceinline__ void cpasync16(uint32_t dst, const void* src, int sz) {
    asm volatile("cp.async.ca.shared.global [%0], [%1], 16, %2;"
        :: "r"(dst), "l"(src), "r"(sz) : "memory");
}
#define CP_COMMIT() asm volatile("cp.async.commit_group;" ::: "memory")
#define CP_WAIT0()  asm volatile("cp.async.wait_group 0;" ::: "memory")

__device__ __forceinline__ uint32_t pack_bf2(float2 v) {
    __nv_bfloat162 h = __floats2bfloat162_rn(v.x, v.y);
    return *reinterpret_cast<uint32_t*>(&h);
}
__device__ __forceinline__ float2 unpack_bf2(uint32_t w) {
    return make_float2(__uint_as_float(w << 16), __uint_as_float(w & 0xFFFF0000u));
}
__device__ __forceinline__ float4 bf4_to_f4(uint2 w) {
    float2 f0 = unpack_bf2(w.x);
    float2 f1 = unpack_bf2(w.y);
    return make_float4(f0.x, f0.y, f1.x, f1.y);
}
__device__ __forceinline__ uint32_t act_bf2(uint32_t w, float2 sc, float2 sh) {
    float2 v = unpack_bf2(w);
    v.x = fmaxf(fmaf(v.x, sc.x, sh.x), 0.f);
    v.y = fmaxf(fmaf(v.y, sc.y, sh.y), 0.f);
    return pack_bf2(v);
}

template <bool HAS_T>
__device__ __forceinline__ float4 act4(float4 v, float4 sc, float4 sh) {
    if (HAS_T) {
        v.x = fmaxf(fmaf(v.x, sc.x, sh.x), 0.f);
        v.y = fmaxf(fmaf(v.y, sc.y, sh.y), 0.f);
        v.z = fmaxf(fmaf(v.z, sc.z, sh.z), 0.f);
        v.w = fmaxf(fmaf(v.w, sc.w, sh.w), 0.f);
    }
    return v;
}

__device__ __forceinline__ void bn_from_stats(const float* st, const float* gamma,
                                              const float* beta, int c,
                                              float& sc, float& sh) {
    const float inv_n = 1.0f / (float)NN;
    float mu = st[c] * inv_n;
    float var = fmaf(-mu, mu, st[HH + c] * inv_n);
    float rinv = rsqrtf(var + 1e-5f);
    sc = rinv * gamma[c];
    sh = fmaf(-mu, sc, beta[c]);
}

__device__ __forceinline__ void mm_issue_copy(const __nv_bfloat16* __restrict__ Ain, int lda,
                                              uint32_t sb, int tile, int buf, int tid) {
    uint32_t base = sb + SM_STG0 + (uint32_t)buf * STGB;
    int row0 = tile * 128;
#pragma unroll
    for (int j = 0; j < 8; j++) {
        int c = tid + 256 * j;
        int r = c >> 4, ch = c & 15;
        int gr = row0 + r;
        uint32_t dst = base + (uint32_t)(r * 272 + ch * 16);
        int ok = (gr < NN) ? 16 : 0;
        const __nv_bfloat16* src = Ain + (size_t)(gr < NN ? gr : 0) * lda + ch * 8;
        cpasync16(dst, src, ok);
    }
}

// ---------------- init: x -> bf16 + W -> bf16 + zero deg/stats ----------------
__global__ void init_kernel(const float* __restrict__ x,
                            const float* __restrict__ W1, const float* __restrict__ W2) {
    int i = blockIdx.x * blockDim.x + threadIdx.x;
    if (i < NN * 32) {
        float4 v = *(const float4*)&x[(size_t)i * 4];
        uint2 o;
        o.x = pack_bf2(make_float2(v.x, v.y));
        o.y = pack_bf2(make_float2(v.z, v.w));
        *(uint2*)&d_xbf[(size_t)i * 4] = o;
    }
    if (i < NN) d_deg[i] = 0;
    if (i < 8 * 256) d_statsA[i] = 0.f;
    if (i < 8 * 16384) {
        int mat = i >> 14, e = i & 16383, l = mat >> 1;
        float v = (mat & 1) ? W2[(size_t)l * 16384 + e] : W1[(size_t)l * 16384 + e];
        d_Wbf[i] = __float2bfloat16(v);
    }
}

// ---------------- aggregation: 2 nodes/warp, 16B/lane gathers, masked tail batch ----------------
template <bool HAS_T>
__global__ void agg_kernel(const __nv_bfloat16* __restrict__ xin, int ldx,
                           const float* __restrict__ stats_in,
                           const float* __restrict__ gamma, const float* __restrict__ beta,
                           const float* __restrict__ eps_ptr, int layer,
                           __nv_bfloat16* __restrict__ u) {
    __shared__ float ssc[HH], ssh[HH];
    int tid = threadIdx.x;
    if (HAS_T) {
        if (tid < HH) bn_from_stats(stats_in, gamma, beta, tid, ssc[tid], ssh[tid]);
        __syncthreads();
    }
    int wid = tid >> 5, lane = tid & 31;
    int half = lane >> 4, hl = lane & 15;
    int node = blockIdx.x * 16 + wid * 2 + half;
    if (node >= NN) return;
    float e = 1.0f + eps_ptr[layer];
    int c0 = hl * 8;
    float sc[8], sh[8];
    if (HAS_T) {
#pragma unroll
        for (int q = 0; q < 8; q++) { sc[q] = ssc[c0 + q]; sh[q] = ssh[c0 + q]; }
    }
    int s = d_off[node], epos = d_off[node + 1];
    float acc[8];
#pragma unroll
    for (int q = 0; q < 8; q++) acc[q] = 0.f;

    uint4 w[8];
    int j = s;
#pragma unroll 1
    for (; j + 8 <= epos; j += 8) {
        int ii[8];
#pragma unroll
        for (int q = 0; q < 8; q++) ii[q] = d_csr[j + q];
#pragma unroll
        for (int q = 0; q < 8; q++)
            w[q] = *(const uint4*)&xin[(size_t)ii[q] * ldx + c0];
#pragma unroll
        for (int q = 0; q < 8; q++) {
            const uint32_t* ww = (const uint32_t*)&w[q];
#pragma unroll
            for (int k = 0; k < 4; k++) {
                float2 v = unpack_bf2(ww[k]);
                if (HAS_T) {
                    v.x = fmaxf(fmaf(v.x, sc[2 * k], sh[2 * k]), 0.f);
                    v.y = fmaxf(fmaf(v.y, sc[2 * k + 1], sh[2 * k + 1]), 0.f);
                }
                acc[2 * k] += v.x;
                acc[2 * k + 1] += v.y;
            }
        }
    }
    // masked tail batch (reuses w[8]; no serial per-edge dependency)
    if (j < epos) {
        int ii[8];
#pragma unroll
        for (int q = 0; q < 8; q++) {
            int jj = j + q;
            ii[q] = (jj < epos) ? d_csr[jj] : node;
        }
#pragma unroll
        for (int q = 0; q < 8; q++)
            w[q] = *(const uint4*)&xin[(size_t)ii[q] * ldx + c0];
#pragma unroll
        for (int q = 0; q < 8; q++) {
            float mq = (j + q < epos) ? 1.f : 0.f;
            const uint32_t* ww = (const uint32_t*)&w[q];
#pragma unroll
            for (int k = 0; k < 4; k++) {
                float2 v = unpack_bf2(ww[k]);
                if (HAS_T) {
                    v.x = fmaxf(fmaf(v.x, sc[2 * k], sh[2 * k]), 0.f);
                    v.y = fmaxf(fmaf(v.y, sc[2 * k + 1], sh[2 * k + 1]), 0.f);
                }
                acc[2 * k]     = fmaf(mq, v.x, acc[2 * k]);
                acc[2 * k + 1] = fmaf(mq, v.y, acc[2 * k + 1]);
            }
        }
    }
    // self term
    {
        uint4 w0 = *(const uint4*)&xin[(size_t)node * ldx + c0];
        const uint32_t* ww = (const uint32_t*)&w0;
#pragma unroll
        for (int k = 0; k < 4; k++) {
            float2 v = unpack_bf2(ww[k]);
            if (HAS_T) {
                v.x = fmaxf(fmaf(v.x, sc[2 * k], sh[2 * k]), 0.f);
                v.y = fmaxf(fmaf(v.y, sc[2 * k + 1], sh[2 * k + 1]), 0.f);
            }
            acc[2 * k] = fmaf(e, v.x, acc[2 * k]);
            acc[2 * k + 1] = fmaf(e, v.y, acc[2 * k + 1]);
        }
    }
    uint4 o;
    uint32_t* oo = (uint32_t*)&o;
#pragma unroll
    for (int k = 0; k < 4; k++)
        oo[k] = pack_bf2(make_float2(acc[2 * k], acc[2 * k + 1]));
    *(uint4*)&u[(size_t)node * HH + c0] = o;
}

// ---------------- persistent pipelined GEMM (R11 structure) ----------------
template <bool HAS_T>
__global__ void __launch_bounds__(256, 1)
mm_hmma_kernel(const __nv_bfloat16* __restrict__ Ain, int lda,
               const float* __restrict__ stats_in,
               const float* __restrict__ gamma, const float* __restrict__ beta,
               const __nv_bfloat16* __restrict__ Wbf,
               const float* __restrict__ bias,
               float* __restrict__ stats_out,
               __nv_bfloat16* __restrict__ Y, int ldy) {
    extern __shared__ char smem[];
    uint32_t sb = smem_u32(smem);
    int tid = threadIdx.x, wid = tid >> 5, lane = tid & 31;
    int gid = lane >> 2, ctib = lane & 3;
    float* sbias = (float*)(smem + SM_BIAS);
    float* ssc   = (float*)(smem + SM_SSC);
    float* ssh   = (float*)(smem + SM_SSH);
    float* sstat = (float*)(smem + SM_STATS);

    if (tid < 128) {
        sbias[tid] = bias[tid];
        if (HAS_T) bn_from_stats(stats_in, gamma, beta, tid, ssc[tid], ssh[tid]);
    }
    sstat[tid] = 0.f;

#pragma unroll
    for (int i = tid; i < 128 * 16; i += 256) {
        int r = i >> 4, c8 = (i & 15) * 8;
        uint32_t dsto = (uint32_t)(r * 272 + c8 * 2);
        *(uint4*)(smem + SM_WH + dsto) = *(const uint4*)&Wbf[r * 128 + c8];
    }

    mm_issue_copy(Ain, lda, sb, blockIdx.x, 0, tid);
    CP_COMMIT();

    float sA[16], sB[16], qA[16], qB[16];
#pragma unroll
    for (int nt = 0; nt < 16; nt++) { sA[nt] = 0.f; sB[nt] = 0.f; qA[nt] = 0.f; qB[nt] = 0.f; }

    int p = 0;
    int r0w = 16 * wid + gid;
#pragma unroll 1
    for (int tile = blockIdx.x; tile < NTILES; tile += MMGRID) {
        CP_WAIT0();
        __syncthreads();

        const char* stg = smem + SM_STG0 + (uint32_t)p * STGB;
        uint32_t ah[32];
#pragma unroll
        for (int k8 = 0; k8 < 8; k8++) {
            uint32_t co = (uint32_t)(k8 * 32 + ctib * 4);
            uint32_t w00 = *(const uint32_t*)(stg + r0w * 272 + co);
            uint32_t w10 = *(const uint32_t*)(stg + (r0w + 8) * 272 + co);
            uint32_t w01 = *(const uint32_t*)(stg + r0w * 272 + co + 16);
            uint32_t w11 = *(const uint32_t*)(stg + (r0w + 8) * 272 + co + 16);
            if (HAS_T) {
                int cc = k8 * 16 + 2 * ctib;
                float2 sa = *(const float2*)&ssc[cc],     ha = *(const float2*)&ssh[cc];
                float2 sc = *(const float2*)&ssc[cc + 8], hc = *(const float2*)&ssh[cc + 8];
                w00 = act_bf2(w00, sa, ha);
                w10 = act_bf2(w10, sa, ha);
                w01 = act_bf2(w01, sc, hc);
                w11 = act_bf2(w11, sc, hc);
            }
            ah[k8 * 4 + 0] = w00;
            ah[k8 * 4 + 1] = w10;
            ah[k8 * 4 + 2] = w01;
            ah[k8 * 4 + 3] = w11;
        }
        __syncthreads();

        int nxt = tile + MMGRID;
        if (nxt < NTILES) mm_issue_copy(Ain, lda, sb, nxt, 1 - p, tid);
        CP_COMMIT();

        int row0 = tile * 128;
        int g = lane & 7, q = (lane >> 3) & 1;
        uint32_t wbase = sb + SM_WH + (uint32_t)(g * 272 + q * 16);
#pragma unroll
        for (int nt = 0; nt < 16; nt++) {
            float ca[4] = {0.f, 0.f, 0.f, 0.f};
            float cb[4] = {0.f, 0.f, 0.f, 0.f};
#pragma unroll
            for (int k8 = 0; k8 < 4; k8++) {
                uint32_t wa = wbase + (uint32_t)(nt * 8 * 272 + k8 * 32);
                uint32_t bh[2], bh2[2];
                ldsm_x2(bh, wa);
                ldsm_x2(bh2, wa + 4 * 32);
                mma_bf16(ca, &ah[k8 * 4], bh);
                mma_bf16(cb, &ah[(k8 + 4) * 4], bh2);
            }
            int col = nt * 8 + 2 * ctib;
            float bx = sbias[col], by = sbias[col + 1];
            float v0 = ca[0] + cb[0] + bx;
            float v1 = ca[1] + cb[1] + by;
            float v2 = ca[2] + cb[2] + bx;
            float v3 = ca[3] + cb[3] + by;
            int gr0 = row0 + r0w, gr1 = gr0 + 8;
            if (gr0 < NN)
                *(uint32_t*)&Y[(size_t)gr0 * ldy + col] = pack_bf2(make_float2(v0, v1));
            else { v0 = 0.f; v1 = 0.f; }
            if (gr1 < NN)
                *(uint32_t*)&Y[(size_t)gr1 * ldy + col] = pack_bf2(make_float2(v2, v3));
            else { v2 = 0.f; v3 = 0.f; }
            sA[nt] += v0 + v2;
            sB[nt] += v1 + v3;
            qA[nt] = fmaf(v0, v0, fmaf(v2, v2, qA[nt]));
            qB[nt] = fmaf(v1, v1, fmaf(v3, v3, qB[nt]));
        }
        p ^= 1;
    }

#pragma unroll
    for (int nt = 0; nt < 16; nt++) {
        float s0 = sA[nt], s1 = sB[nt], q0 = qA[nt], q1 = qB[nt];
#pragma unroll
        for (int h = 4; h < 32; h <<= 1) {
            s0 += __shfl_xor_sync(0xffffffffu, s0, h);
            s1 += __shfl_xor_sync(0xffffffffu, s1, h);
            q0 += __shfl_xor_sync(0xffffffffu, q0, h);
            q1 += __shfl_xor_sync(0xffffffffu, q1, h);
        }
        if (lane < 4) {
            int col = nt * 8 + 2 * lane;
            atomicAdd(&sstat[col], s0);
            atomicAdd(&sstat[col + 1], s1);
            atomicAdd(&sstat[128 + col], q0);
            atomicAdd(&sstat[128 + col + 1], q1);
        }
    }
    __syncthreads();
    atomicAdd(&stats_out[tid], sstat[tid]);
}

// ---------------- CSR build ----------------
__global__ void count_kernel(const int* __restrict__ dst) {
    int i = blockIdx.x * blockDim.x + threadIdx.x;
    if (i < EE) atomicAdd(&d_deg[dst[i]], 1);
}

__global__ void scan1_kernel() {
    __shared__ int wsum[32];
    int t = threadIdx.x, lane = t & 31, w = t >> 5;
    int idx = blockIdx.x * 1024 + t;
    int v = (idx < NN) ? d_deg[idx] : 0;
    int x = v;
#pragma unroll
    for (int d = 1; d < 32; d <<= 1) {
        int y = __shfl_up_sync(0xffffffffu, x, d);
        if (lane >= d) x += y;
    }
    if (lane == 31) wsum[w] = x;
    __syncthreads();
    if (w == 0) {
        int s = wsum[lane];
#pragma unroll
        for (int d = 1; d < 32; d <<= 1) {
            int y = __shfl_up_sync(0xffffffffu, s, d);
            if (lane >= d) s += y;
        }
        wsum[lane] = s;
    }
    __syncthreads();
    int woff = (w > 0) ? wsum[w - 1] : 0;
    int excl = woff + x - v;
    if (idx < NN) d_off[idx] = excl;
    if (t == 1023) d_bsum[blockIdx.x] = woff + x;
}

__global__ void scan2_kernel() {
    __shared__ int bs[SCAN_NB];
    __shared__ int boff_s;
    int t = threadIdx.x;
    if (t < SCAN_NB) bs[t] = d_bsum[t];
    __syncthreads();
    if (t == 0) {
        int acc = 0;
#pragma unroll 1
        for (int b = 0; b < (int)blockIdx.x; b++) acc += bs[b];
        boff_s = acc;
        if (blockIdx.x == SCAN_NB - 1) {
            int tot = acc;
            for (int b = blockIdx.x; b < SCAN_NB; b++) tot += bs[b];
            d_off[NN] = tot;
        }
    }
    __syncthreads();
    int boff = boff_s;
    int idx = blockIdx.x * 1024 + t;
    if (idx < NN) {
        int val = d_off[idx] + boff;
        d_off[idx] = val;
        d_cursor[idx] = val;
    }
}

__global__ void fill_kernel(const int* __restrict__ src, const int* __restrict__ dst) {
    int i = blockIdx.x * blockDim.x + threadIdx.x;
    if (i < EE) {
        int p = atomicAdd(&d_cursor[dst[i]], 1);
        d_csr[p] = src[i];
    }
}

// ---------------- pooling offsets (both levels in one launch) ----------------
__global__ void offsets_kernel(const int* __restrict__ n2s, const int* __restrict__ s2g) {
    int i = blockIdx.x * blockDim.x + threadIdx.x;
    if (i <= SS) {
        int lo = 0, hi = NN;
        while (lo < hi) {
            int mid = (lo + hi) >> 1;
            if (n2s[mid] < i) lo = mid + 1; else hi = mid;
        }
        d_suboff[i] = lo;
    }
    int g = i - (SS + 1);
    if (g >= 0 && g <= GG) {
        int lo = 0, hi = SS;
        while (lo < hi) {
            int mid = (lo + hi) >> 1;
            if (s2g[mid] < g) lo = mid + 1; else hi = mid;
        }
        d_gphoff[g] = lo;
    }
}

__global__ void segmean1_kernel(const __nv_bfloat16* __restrict__ in, const int* __restrict__ off,
                                float* __restrict__ out,
                                const float* __restrict__ statsA,
                                const float* __restrict__ g2, const float* __restrict__ be2) {
    int s = blockIdx.x, t = threadIdx.x;
    int lt = t >> 5;
    int c0 = (t & 31) * 4;
    const float* st = statsA + (size_t)(2 * lt + 1) * 256;
    float4 sc4, sh4;
    {
        float sc, sh;
        bn_from_stats(st, g2 + lt * HH, be2 + lt * HH, c0 + 0, sc, sh); sc4.x = sc; sh4.x = sh;
        bn_from_stats(st, g2 + lt * HH, be2 + lt * HH, c0 + 1, sc, sh); sc4.y = sc; sh4.y = sh;
        bn_from_stats(st, g2 + lt * HH, be2 + lt * HH, c0 + 2, sc, sh); sc4.z = sc; sh4.z = sh;
        bn_from_stats(st, g2 + lt * HH, be2 + lt * HH, c0 + 3, sc, sh); sc4.w = sc; sh4.w = sh;
    }
    int r0 = off[s], r1 = off[s + 1];
    float4 acc = make_float4(0.f, 0.f, 0.f, 0.f);
    for (int r = r0; r < r1; r++) {
        float4 v = bf4_to_f4(*(const uint2*)&in[(size_t)r * (LL * HH) + t * 4]);
        v = act4<true>(v, sc4, sh4);
        acc.x += v.x; acc.y += v.y; acc.z += v.z; acc.w += v.w;
    }
    float inv = 1.0f / fmaxf((float)(r1 - r0), 1.0f);
    float4 o = make_float4(acc.x * inv, acc.y * inv, acc.z * inv, acc.w * inv);
    *(float4*)&out[(size_t)s * (LL * HH) + t * 4] = o;
}

__global__ void segmean2_kernel(const float* __restrict__ in, const int* __restrict__ off,
                                float* __restrict__ out) {
    int s = blockIdx.x, t = threadIdx.x;
    int r0 = off[s], r1 = off[s + 1];
    float4 acc = make_float4(0.f, 0.f, 0.f, 0.f);
    for (int r = r0; r < r1; r++) {
        float4 v = *(const float4*)&in[(size_t)r * (LL * HH) + t * 4];
        acc.x += v.x; acc.y += v.y; acc.z += v.z; acc.w += v.w;
    }
    float inv = 1.0f / fmaxf((float)(r1 - r0), 1.0f);
    float4 o = make_float4(acc.x * inv, acc.y * inv, acc.z * inv, acc.w * inv);
    *(float4*)&out[(size_t)s * (LL * HH) + t * 4] = o;
}

// ---------------- head ----------------
__global__ void head_kernel(const float* __restrict__ gph,
                            const float* __restrict__ w1, const float* __restrict__ bb1,
                            const float* __restrict__ w2, const float* __restrict__ bb2,
                            float* __restrict__ out) {
    __shared__ float grow[LL * HH];
    __shared__ float hbuf[HH];
    __shared__ float obuf[CC];
    int g = blockIdx.x, t = threadIdx.x;
    for (int i = t; i < LL * HH; i += 128) grow[i] = gph[(size_t)g * (LL * HH) + i];
    __syncthreads();
    float acc = bb1[t];
#pragma unroll 8
    for (int k = 0; k < LL * HH; k++) acc = fmaf(grow[k], w1[(size_t)t * (LL * HH) + k], acc);
    hbuf[t] = fmaxf(acc, 0.f);
    __syncthreads();
    if (t < CC) {
        float a = bb2[t];
#pragma unroll 8
        for (int k = 0; k < HH; k++) a = fmaf(hbuf[k], w2[t * HH + k], a);
        obuf[t] = a;
    }
    __syncthreads();
    if (t == 0) {
        float m = obuf[0];
#pragma unroll
        for (int j = 1; j < CC; j++) m = fmaxf(m, obuf[j]);
        float se = 0.f;
#pragma unroll
        for (int j = 0; j < CC; j++) se += expf(obuf[j] - m);
        float lse = m + logf(se);
#pragma unroll
        for (int j = 0; j < CC; j++) out[g * CC + j] = obuf[j] - lse;
    }
}

// ---------------- launcher ----------------
extern "C" void kernel_launch(void* const* d_in, const int* in_sizes, int n_in,
                              void* d_out, int out_size) {
    const float* x     = (const float*)d_in[0];
    const int*   ei    = (const int*)d_in[1];
    const int*   n2s   = (const int*)d_in[2];
    const int*   s2g   = (const int*)d_in[3];
    const float* W1    = (const float*)d_in[4];
    const float* b1    = (const float*)d_in[5];
    const float* g1    = (const float*)d_in[6];
    const float* be1   = (const float*)d_in[7];
    const float* W2    = (const float*)d_in[8];
    const float* b2    = (const float*)d_in[9];
    const float* g2    = (const float*)d_in[10];
    const float* be2   = (const float*)d_in[11];
    const float* eps   = (const float*)d_in[12];
    const float* lin1W = (const float*)d_in[13];
    const float* lin1b = (const float*)d_in[14];
    const float* lin2W = (const float*)d_in[15];
    const float* lin2b = (const float*)d_in[16];
    float* out = (float*)d_out;

    void* p;
    cudaGetSymbolAddress(&p, d_ubf);    __nv_bfloat16* ubfp   = (__nv_bfloat16*)p;
    cudaGetSymbolAddress(&p, d_tbf);    __nv_bfloat16* tbfp   = (__nv_bfloat16*)p;
    cudaGetSymbolAddress(&p, d_xbf);    __nv_bfloat16* xbfp   = (__nv_bfloat16*)p;
    cudaGetSymbolAddress(&p, d_featbf); __nv_bfloat16* featp  = (__nv_bfloat16*)p;
    cudaGetSymbolAddress(&p, d_statsA); float* statsp  = (float*)p;
    cudaGetSymbolAddress(&p, d_sub);    float* subp    = (float*)p;
    cudaGetSymbolAddress(&p, d_gph);    float* gphp    = (float*)p;
    cudaGetSymbolAddress(&p, d_suboff); int* suboffp   = (int*)p;
    cudaGetSymbolAddress(&p, d_gphoff); int* gphoffp   = (int*)p;
    cudaGetSymbolAddress(&p, d_Wbf);    __nv_bfloat16* wbfp = (__nv_bfloat16*)p;

    cudaFuncSetAttribute((const void*)mm_hmma_kernel<false>,
                         cudaFuncAttributeMaxDynamicSharedMemorySize, MM_SMEM);
    cudaFuncSetAttribute((const void*)mm_hmma_kernel<true>,
                         cudaFuncAttributeMaxDynamicSharedMemorySize, MM_SMEM);

    const int* src = ei;
    const int* dst = ei + EE;

    init_kernel<<<(NN * 32 + 255) / 256, 256>>>(x, W1, W2);

    count_kernel<<<(EE + 255) / 256, 256>>>(dst);
    scan1_kernel<<<SCAN_NB, 1024>>>();
    scan2_kernel<<<SCAN_NB, 1024>>>();
    fill_kernel<<<(EE + 255) / 256, 256>>>(src, dst);

    const int agg_blocks = (NN + 15) / 16;
    for (int l = 0; l < LL; l++) {
        const __nv_bfloat16* w1bf = wbfp + (size_t)(l * 2) * 16384;
        const __nv_bfloat16* w2bf = wbfp + (size_t)(l * 2 + 1) * 16384;
        float* st1 = statsp + (size_t)(2 * l) * 256;
        float* st2 = statsp + (size_t)(2 * l + 1) * 256;

        if (l == 0) {
            agg_kernel<false><<<agg_blocks, 256>>>(
                xbfp, FF, nullptr, nullptr, nullptr, eps, 0, ubfp);
        } else {
            agg_kernel<true><<<agg_blocks, 256>>>(
                featp + (size_t)(l - 1) * HH, LL * HH,
                statsp + (size_t)(2 * (l - 1) + 1) * 256,
                g2 + (size_t)(l - 1) * HH, be2 + (size_t)(l - 1) * HH, eps, l, ubfp);
        }

        mm_hmma_kernel<false><<<MMGRID, 256, MM_SMEM>>>(
            ubfp, HH, nullptr, nullptr, nullptr, w1bf,
            b1 + (size_t)l * HH, st1, tbfp, HH);

        mm_hmma_kernel<true><<<MMGRID, 256, MM_SMEM>>>(
            tbfp, HH, st1, g1 + (size_t)l * HH, be1 + (size_t)l * HH,
            w2bf, b2 + (size_t)l * HH, st2,
            featp + (size_t)l * HH, LL * HH);
    }

    offsets_kernel<<<(SS + GG + 2 + 255) / 256, 256>>>(n2s, s2g);
    segmean1_kernel<<<SS, 128>>>(featp, suboffp, subp, statsp, g2, be2);
    segmean2_kernel<<<GG, 128>>>(subp, gphoffp, gphp);

    head_kernel<<<GG, 128>>>(gphp, lin1W, lin1b, lin2W, lin2b, out);
}

// round 14
// speedup vs baseline: 1.1585x; 1.0752x over previous
#include <cuda_runtime.h>
#include <cuda_bf16.h>
#include <cstdint>
#include <cstddef>

#define NN 100000
#define EE 1600000
#define FF 128
#define HH 128
#define LL 4
#define SS 10000
#define GG 256
#define CC 10
#define SCAN_NB 98
#define NTILES 782
#define MMGRID 148

// ---------------- scratch (device globals; no allocation allowed) ----------------
__device__ int   d_deg[NN];
__device__ int   d_off[NN + 1];
__device__ int   d_cursor[NN];
__device__ int   d_csr[EE];
__device__ int   d_bsum[SCAN_NB];
__device__ __nv_bfloat16 d_ubf[(size_t)NN * HH];
__device__ __nv_bfloat16 d_tbf[(size_t)NN * HH];
__device__ __nv_bfloat16 d_xbf[(size_t)NN * FF];
__device__ __nv_bfloat16 d_featbf[(size_t)NN * LL * HH];
__device__ float d_statsA[8 * 256];
__device__ int   d_suboff[SS + 1];
__device__ int   d_gphoff[GG + 1];
__device__ float d_sub[(size_t)SS * LL * HH];
__device__ float d_gph[(size_t)GG * LL * HH];
__device__ __nv_bfloat16 d_Wbf[8 * 128 * 128];

// ---------------- smem layout for persistent mm kernel ----------------
#define SM_BIAS  0
#define SM_SSC   512
#define SM_SSH   1024
#define SM_STATS 1536
#define SM_WH    2560
#define SM_STG0  (SM_WH + 34816)      // 37376
#define STGB     34816                // 128 rows * 272B (bf16 stage)
#define SM_STG1  (SM_STG0 + STGB)     // 72192
#define MM_SMEM  (SM_STG1 + STGB)     // 107008

__device__ __forceinline__ uint32_t smem_u32(const void* p) {
    uint32_t a;
    asm("{ .reg .u64 t; cvta.to.shared.u64 t, %1; cvt.u32.u64 %0, t; }" : "=r"(a) : "l"(p));
    return a;
}
__device__ __forceinline__ void ldsm_x2(uint32_t* b, uint32_t addr) {
    asm volatile("ldmatrix.sync.aligned.m8n8.x2.shared.b16 {%0,%1}, [%2];"
        : "=r"(b[0]), "=r"(b[1]) : "r"(addr));
}
__device__ __forceinline__ void mma_bf16(float* c, const uint32_t* a, const uint32_t* b) {
    asm volatile("mma.sync.aligned.m16n8k16.row.col.f32.bf16.bf16.f32 "
        "{%0,%1,%2,%3}, {%4,%5,%6,%7}, {%8,%9}, {%0,%1,%2,%3};"
        : "+f"(c[0]), "+f"(c[1]), "+f"(c[2]), "+f"(c[3])
        : "r"(a[0]), "r"(a[1]), "r"(a[2]), "r"(a[3]), "r"(b[0]), "r"(b[1]));
}
__device__ __forceinline__ void cpasync16(uint32_t dst, const void* src, int sz) {
    asm volatile("cp.async.ca.shared.global [%0], [%1], 16, %2;"
        :: "r"(dst), "l"(src), "r"(sz) : "memory");
}
#define CP_COMMIT() asm volatile("cp.async.commit_group;" ::: "memory")
#define CP_WAIT0()  asm volatile("cp.async.wait_group 0;" ::: "memory")

__device__ __forceinline__ uint32_t pack_bf2(float2 v) {
    __nv_bfloat162 h = __floats2bfloat162_rn(v.x, v.y);
    return *reinterpret_cast<uint32_t*>(&h);
}
__device__ __forceinline__ float2 unpack_bf2(uint32_t w) {
    return make_float2(__uint_as_float(w << 16), __uint_as_float(w & 0xFFFF0000u));
}
__device__ __forceinline__ float4 bf4_to_f4(uint2 w) {
    float2 f0 = unpack_bf2(w.x);
    float2 f1 = unpack_bf2(w.y);
    return make_float4(f0.x, f0.y, f1.x, f1.y);
}
__device__ __forceinline__ uint32_t act_bf2(uint32_t w, float2 sc, float2 sh) {
    float2 v = unpack_bf2(w);
    v.x = fmaxf(fmaf(v.x, sc.x, sh.x), 0.f);
    v.y = fmaxf(fmaf(v.y, sc.y, sh.y), 0.f);
    return pack_bf2(v);
}

template <bool HAS_T>
__device__ __forceinline__ float4 act4(float4 v, float4 sc, float4 sh) {
    if (HAS_T) {
        v.x = fmaxf(fmaf(v.x, sc.x, sh.x), 0.f);
        v.y = fmaxf(fmaf(v.y, sc.y, sh.y), 0.f);
        v.z = fmaxf(fmaf(v.z, sc.z, sh.z), 0.f);
        v.w = fmaxf(fmaf(v.w, sc.w, sh.w), 0.f);
    }
    return v;
}

__device__ __forceinline__ void bn_from_stats(const float* st, const float* gamma,
                                              const float* beta, int c,
                                              float& sc, float& sh) {
    const float inv_n = 1.0f / (float)NN;
    float mu = st[c] * inv_n;
    float var = fmaf(-mu, mu, st[HH + c] * inv_n);
    float rinv = rsqrtf(var + 1e-5f);
    sc = rinv * gamma[c];
    sh = fmaf(-mu, sc, beta[c]);
}

__device__ __forceinline__ void mm_issue_copy(const __nv_bfloat16* __restrict__ Ain, int lda,
                                              uint32_t sb, int tile, int buf, int tid) {
    uint32_t base = sb + SM_STG0 + (uint32_t)buf * STGB;
    int row0 = tile * 128;
#pragma unroll
    for (int j = 0; j < 8; j++) {
        int c = tid + 256 * j;
        int r = c >> 4, ch = c & 15;
        int gr = row0 + r;
        uint32_t dst = base + (uint32_t)(r * 272 + ch * 16);
        int ok = (gr < NN) ? 16 : 0;
        const __nv_bfloat16* src = Ain + (size_t)(gr < NN ? gr : 0) * lda + ch * 8;
        cpasync16(dst, src, ok);
    }
}

// ---------------- init: x -> bf16 + W -> bf16 + zero deg/stats ----------------
__global__ void init_kernel(const float* __restrict__ x,
                            const float* __restrict__ W1, const float* __restrict__ W2) {
    int i = blockIdx.x * blockDim.x + threadIdx.x;
    if (i < NN * 32) {
        float4 v = *(const float4*)&x[(size_t)i * 4];
        uint2 o;
        o.x = pack_bf2(make_float2(v.x, v.y));
        o.y = pack_bf2(make_float2(v.z, v.w));
        *(uint2*)&d_xbf[(size_t)i * 4] = o;
    }
    if (i < NN) d_deg[i] = 0;
    if (i < 8 * 256) d_statsA[i] = 0.f;
    if (i < 8 * 16384) {
        int mat = i >> 14, e = i & 16383, l = mat >> 1;
        float v = (mat & 1) ? W2[(size_t)l * 16384 + e] : W1[(size_t)l * 16384 + e];
        d_Wbf[i] = __float2bfloat16(v);
    }
}

// ---------------- aggregation: 2 nodes/warp, 16B/lane gathers (R11 shape) ----------------
template <bool HAS_T>
__global__ void agg_kernel(const __nv_bfloat16* __restrict__ xin, int ldx,
                           const float* __restrict__ stats_in,
                           const float* __restrict__ gamma, const float* __restrict__ beta,
                           const float* __restrict__ eps_ptr, int layer,
                           __nv_bfloat16* __restrict__ u) {
    __shared__ float ssc[HH], ssh[HH];
    int tid = threadIdx.x;
    if (HAS_T) {
        if (tid < HH) bn_from_stats(stats_in, gamma, beta, tid, ssc[tid], ssh[tid]);
        __syncthreads();
    }
    int wid = tid >> 5, lane = tid & 31;
    int half = lane >> 4, hl = lane & 15;
    int node = blockIdx.x * 16 + wid * 2 + half;
    if (node >= NN) return;
    float e = 1.0f + eps_ptr[layer];
    int c0 = hl * 8;
    float sc[8], sh[8];
    if (HAS_T) {
#pragma unroll
        for (int q = 0; q < 8; q++) { sc[q] = ssc[c0 + q]; sh[q] = ssh[c0 + q]; }
    }
    int s = d_off[node], epos = d_off[node + 1];
    float acc[8];
#pragma unroll
    for (int q = 0; q < 8; q++) acc[q] = 0.f;

    int j = s;
#pragma unroll 1
    for (; j + 8 <= epos; j += 8) {
        int ii[8];
#pragma unroll
        for (int q = 0; q < 8; q++) ii[q] = d_csr[j + q];
        uint4 w[8];
#pragma unroll
        for (int q = 0; q < 8; q++)
            w[q] = *(const uint4*)&xin[(size_t)ii[q] * ldx + c0];
#pragma unroll
        for (int q = 0; q < 8; q++) {
            const uint32_t* ww = (const uint32_t*)&w[q];
#pragma unroll
            for (int k = 0; k < 4; k++) {
                float2 v = unpack_bf2(ww[k]);
                if (HAS_T) {
                    v.x = fmaxf(fmaf(v.x, sc[2 * k], sh[2 * k]), 0.f);
                    v.y = fmaxf(fmaf(v.y, sc[2 * k + 1], sh[2 * k + 1]), 0.f);
                }
                acc[2 * k] += v.x;
                acc[2 * k + 1] += v.y;
            }
        }
    }
#pragma unroll 1
    for (; j < epos; ++j) {
        int i0 = d_csr[j];
        uint4 w0 = *(const uint4*)&xin[(size_t)i0 * ldx + c0];
        const uint32_t* ww = (const uint32_t*)&w0;
#pragma unroll
        for (int k = 0; k < 4; k++) {
            float2 v = unpack_bf2(ww[k]);
            if (HAS_T) {
                v.x = fmaxf(fmaf(v.x, sc[2 * k], sh[2 * k]), 0.f);
                v.y = fmaxf(fmaf(v.y, sc[2 * k + 1], sh[2 * k + 1]), 0.f);
            }
            acc[2 * k] += v.x;
            acc[2 * k + 1] += v.y;
        }
    }
    // self term
    {
        uint4 w0 = *(const uint4*)&xin[(size_t)node * ldx + c0];
        const uint32_t* ww = (const uint32_t*)&w0;
#pragma unroll
        for (int k = 0; k < 4; k++) {
            float2 v = unpack_bf2(ww[k]);
            if (HAS_T) {
                v.x = fmaxf(fmaf(v.x, sc[2 * k], sh[2 * k]), 0.f);
                v.y = fmaxf(fmaf(v.y, sc[2 * k + 1], sh[2 * k + 1]), 0.f);
            }
            acc[2 * k] = fmaf(e, v.x, acc[2 * k]);
            acc[2 * k + 1] = fmaf(e, v.y, acc[2 * k + 1]);
        }
    }
    uint4 o;
    uint32_t* oo = (uint32_t*)&o;
#pragma unroll
    for (int k = 0; k < 4; k++)
        oo[k] = pack_bf2(make_float2(acc[2 * k], acc[2 * k + 1]));
    *(uint4*)&u[(size_t)node * HH + c0] = o;
}

// ---------------- persistent pipelined GEMM (R11 structure, verbatim) ----------------
template <bool HAS_T>
__global__ void __launch_bounds__(256, 1)
mm_hmma_kernel(const __nv_bfloat16* __restrict__ Ain, int lda,
               const float* __restrict__ stats_in,
               const float* __restrict__ gamma, const float* __restrict__ beta,
               const __nv_bfloat16* __restrict__ Wbf,
               const float* __restrict__ bias,
               float* __restrict__ stats_out,
               __nv_bfloat16* __restrict__ Y, int ldy) {
    extern __shared__ char smem[];
    uint32_t sb = smem_u32(smem);
    int tid = threadIdx.x, wid = tid >> 5, lane = tid & 31;
    int gid = lane >> 2, ctib = lane & 3;
    float* sbias = (float*)(smem + SM_BIAS);
    float* ssc   = (float*)(smem + SM_SSC);
    float* ssh   = (float*)(smem + SM_SSH);
    float* sstat = (float*)(smem + SM_STATS);

    if (tid < 128) {
        sbias[tid] = bias[tid];
        if (HAS_T) bn_from_stats(stats_in, gamma, beta, tid, ssc[tid], ssh[tid]);
    }
    sstat[tid] = 0.f;

#pragma unroll
    for (int i = tid; i < 128 * 16; i += 256) {
        int r = i >> 4, c8 = (i & 15) * 8;
        uint32_t dsto = (uint32_t)(r * 272 + c8 * 2);
        *(uint4*)(smem + SM_WH + dsto) = *(const uint4*)&Wbf[r * 128 + c8];
    }

    mm_issue_copy(Ain, lda, sb, blockIdx.x, 0, tid);
    CP_COMMIT();

    float sA[16], sB[16], qA[16], qB[16];
#pragma unroll
    for (int nt = 0; nt < 16; nt++) { sA[nt] = 0.f; sB[nt] = 0.f; qA[nt] = 0.f; qB[nt] = 0.f; }

    int p = 0;
    int r0w = 16 * wid + gid;
#pragma unroll 1
    for (int tile = blockIdx.x; tile < NTILES; tile += MMGRID) {
        CP_WAIT0();
        __syncthreads();

        const char* stg = smem + SM_STG0 + (uint32_t)p * STGB;
        uint32_t ah[32];
#pragma unroll
        for (int k8 = 0; k8 < 8; k8++) {
            uint32_t co = (uint32_t)(k8 * 32 + ctib * 4);
            uint32_t w00 = *(const uint32_t*)(stg + r0w * 272 + co);
            uint32_t w10 = *(const uint32_t*)(stg + (r0w + 8) * 272 + co);
            uint32_t w01 = *(const uint32_t*)(stg + r0w * 272 + co + 16);
            uint32_t w11 = *(const uint32_t*)(stg + (r0w + 8) * 272 + co + 16);
            if (HAS_T) {
                int cc = k8 * 16 + 2 * ctib;
                float2 sa = *(const float2*)&ssc[cc],     ha = *(const float2*)&ssh[cc];
                float2 sc = *(const float2*)&ssc[cc + 8], hc = *(const float2*)&ssh[cc + 8];
                w00 = act_bf2(w00, sa, ha);
                w10 = act_bf2(w10, sa, ha);
                w01 = act_bf2(w01, sc, hc);
                w11 = act_bf2(w11, sc, hc);
            }
            ah[k8 * 4 + 0] = w00;
            ah[k8 * 4 + 1] = w10;
            ah[k8 * 4 + 2] = w01;
            ah[k8 * 4 + 3] = w11;
        }
        __syncthreads();

        int nxt = tile + MMGRID;
        if (nxt < NTILES) mm_issue_copy(Ain, lda, sb, nxt, 1 - p, tid);
        CP_COMMIT();

        int row0 = tile * 128;
        int g = lane & 7, q = (lane >> 3) & 1;
        uint32_t wbase = sb + SM_WH + (uint32_t)(g * 272 + q * 16);
#pragma unroll
        for (int nt = 0; nt < 16; nt++) {
            float ca[4] = {0.f, 0.f, 0.f, 0.f};
            float cb[4] = {0.f, 0.f, 0.f, 0.f};
#pragma unroll
            for (int k8 = 0; k8 < 4; k8++) {
                uint32_t wa = wbase + (uint32_t)(nt * 8 * 272 + k8 * 32);
                uint32_t bh[2], bh2[2];
                ldsm_x2(bh, wa);
                ldsm_x2(bh2, wa + 4 * 32);
                mma_bf16(ca, &ah[k8 * 4], bh);
                mma_bf16(cb, &ah[(k8 + 4) * 4], bh2);
            }
            int col = nt * 8 + 2 * ctib;
            float bx = sbias[col], by = sbias[col + 1];
            float v0 = ca[0] + cb[0] + bx;
            float v1 = ca[1] + cb[1] + by;
            float v2 = ca[2] + cb[2] + bx;
            float v3 = ca[3] + cb[3] + by;
            int gr0 = row0 + r0w, gr1 = gr0 + 8;
            if (gr0 < NN)
                *(uint32_t*)&Y[(size_t)gr0 * ldy + col] = pack_bf2(make_float2(v0, v1));
            else { v0 = 0.f; v1 = 0.f; }
            if (gr1 < NN)
                *(uint32_t*)&Y[(size_t)gr1 * ldy + col] = pack_bf2(make_float2(v2, v3));
            else { v2 = 0.f; v3 = 0.f; }
            sA[nt] += v0 + v2;
            sB[nt] += v1 + v3;
            qA[nt] = fmaf(v0, v0, fmaf(v2, v2, qA[nt]));
            qB[nt] = fmaf(v1, v1, fmaf(v3, v3, qB[nt]));
        }
        p ^= 1;
    }

#pragma unroll
    for (int nt = 0; nt < 16; nt++) {
        float s0 = sA[nt], s1 = sB[nt], q0 = qA[nt], q1 = qB[nt];
#pragma unroll
        for (int h = 4; h < 32; h <<= 1) {
            s0 += __shfl_xor_sync(0xffffffffu, s0, h);
            s1 += __shfl_xor_sync(0xffffffffu, s1, h);
            q0 += __shfl_xor_sync(0xffffffffu, q0, h);
            q1 += __shfl_xor_sync(0xffffffffu, q1, h);
        }
        if (lane < 4) {
            int col = nt * 8 + 2 * lane;
            atomicAdd(&sstat[col], s0);
            atomicAdd(&sstat[col + 1], s1);
            atomicAdd(&sstat[128 + col], q0);
            atomicAdd(&sstat[128 + col + 1], q1);
        }
    }
    __syncthreads();
    atomicAdd(&stats_out[tid], sstat[tid]);
}

// ---------------- CSR build ----------------
__global__ void count_kernel(const int* __restrict__ dst) {
    int i = blockIdx.x * blockDim.x + threadIdx.x;
    if (i < EE) atomicAdd(&d_deg[dst[i]], 1);
}

__global__ void scan1_kernel() {
    __shared__ int wsum[32];
    int t = threadIdx.x, lane = t & 31, w = t >> 5;
    int idx = blockIdx.x * 1024 + t;
    int v = (idx < NN) ? d_deg[idx] : 0;
    int x = v;
#pragma unroll
    for (int d = 1; d < 32; d <<= 1) {
        int y = __shfl_up_sync(0xffffffffu, x, d);
        if (lane >= d) x += y;
    }
    if (lane == 31) wsum[w] = x;
    __syncthreads();
    if (w == 0) {
        int s = wsum[lane];
#pragma unroll
        for (int d = 1; d < 32; d <<= 1) {
            int y = __shfl_up_sync(0xffffffffu, s, d);
            if (lane >= d) s += y;
        }
        wsum[lane] = s;
    }
    __syncthreads();
    int woff = (w > 0) ? wsum[w - 1] : 0;
    int excl = woff + x - v;
    if (idx < NN) d_off[idx] = excl;
    if (t == 1023) d_bsum[blockIdx.x] = woff + x;
}

__global__ void scan2_kernel() {
    __shared__ int bs[SCAN_NB];
    __shared__ int boff_s;
    int t = threadIdx.x;
    if (t < SCAN_NB) bs[t] = d_bsum[t];
    __syncthreads();
    if (t == 0) {
        int acc = 0;
#pragma unroll 1
        for (int b = 0; b < (int)blockIdx.x; b++) acc += bs[b];
        boff_s = acc;
        if (blockIdx.x == SCAN_NB - 1) {
            int tot = acc;
            for (int b = blockIdx.x; b < SCAN_NB; b++) tot += bs[b];
            d_off[NN] = tot;
        }
    }
    __syncthreads();
    int boff = boff_s;
    int idx = blockIdx.x * 1024 + t;
    if (idx < NN) {
        int val = d_off[idx] + boff;
        d_off[idx] = val;
        d_cursor[idx] = val;
    }
}

__global__ void fill_kernel(const int* __restrict__ src, const int* __restrict__ dst) {
    int i = blockIdx.x * blockDim.x + threadIdx.x;
    if (i < EE) {
        int p = atomicAdd(&d_cursor[dst[i]], 1);
        d_csr[p] = src[i];
    }
}

// ---------------- pooling offsets (both levels in one launch) ----------------
__global__ void offsets_kernel(const int* __restrict__ n2s, const int* __restrict__ s2g) {
    int i = blockIdx.x * blockDim.x + threadIdx.x;
    if (i <= SS) {
        int lo = 0, hi = NN;
        while (lo < hi) {
            int mid = (lo + hi) >> 1;
            if (n2s[mid] < i) lo = mid + 1; else hi = mid;
        }
        d_suboff[i] = lo;
    }
    int g = i - (SS + 1);
    if (g >= 0 && g <= GG) {
        int lo = 0, hi = SS;
        while (lo < hi) {
            int mid = (lo + hi) >> 1;
            if (s2g[mid] < g) lo = mid + 1; else hi = mid;
        }
        d_gphoff[g] = lo;
    }
}

__global__ void segmean1_kernel(const __nv_bfloat16* __restrict__ in, const int* __restrict__ off,
                                float* __restrict__ out,
                                const float* __restrict__ statsA,
                                const float* __restrict__ g2, const float* __restrict__ be2) {
    int s = blockIdx.x, t = threadIdx.x;
    int lt = t >> 5;
    int c0 = (t & 31) * 4;
    const float* st = statsA + (size_t)(2 * lt + 1) * 256;
    float4 sc4, sh4;
    {
        float sc, sh;
        bn_from_stats(st, g2 + lt * HH, be2 + lt * HH, c0 + 0, sc, sh); sc4.x = sc; sh4.x = sh;
        bn_from_stats(st, g2 + lt * HH, be2 + lt * HH, c0 + 1, sc, sh); sc4.y = sc; sh4.y = sh;
        bn_from_stats(st, g2 + lt * HH, be2 + lt * HH, c0 + 2, sc, sh); sc4.z = sc; sh4.z = sh;
        bn_from_stats(st, g2 + lt * HH, be2 + lt * HH, c0 + 3, sc, sh); sc4.w = sc; sh4.w = sh;
    }
    int r0 = off[s], r1 = off[s + 1];
    float4 acc = make_float4(0.f, 0.f, 0.f, 0.f);
    for (int r = r0; r < r1; r++) {
        float4 v = bf4_to_f4(*(const uint2*)&in[(size_t)r * (LL * HH) + t * 4]);
        v = act4<true>(v, sc4, sh4);
        acc.x += v.x; acc.y += v.y; acc.z += v.z; acc.w += v.w;
    }
    float inv = 1.0f / fmaxf((float)(r1 - r0), 1.0f);
    float4 o = make_float4(acc.x * inv, acc.y * inv, acc.z * inv, acc.w * inv);
    *(float4*)&out[(size_t)s * (LL * HH) + t * 4] = o;
}

__global__ void segmean2_kernel(const float* __restrict__ in, const int* __restrict__ off,
                                float* __restrict__ out) {
    int s = blockIdx.x, t = threadIdx.x;
    int r0 = off[s], r1 = off[s + 1];
    float4 acc = make_float4(0.f, 0.f, 0.f, 0.f);
    for (int r = r0; r < r1; r++) {
        float4 v = *(const float4*)&in[(size_t)r * (LL * HH) + t * 4];
        acc.x += v.x; acc.y += v.y; acc.z += v.z; acc.w += v.w;
    }
    float inv = 1.0f / fmaxf((float)(r1 - r0), 1.0f);
    float4 o = make_float4(acc.x * inv, acc.y * inv, acc.z * inv, acc.w * inv);
    *(float4*)&out[(size_t)s * (LL * HH) + t * 4] = o;
}

// ---------------- head ----------------
__global__ void head_kernel(const float* __restrict__ gph,
                            const float* __restrict__ w1, const float* __restrict__ bb1,
                            const float* __restrict__ w2, const float* __restrict__ bb2,
                            float* __restrict__ out) {
    __shared__ float grow[LL * HH];
    __shared__ float hbuf[HH];
    __shared__ float obuf[CC];
    int g = blockIdx.x, t = threadIdx.x;
    for (int i = t; i < LL * HH; i += 128) grow[i] = gph[(size_t)g * (LL * HH) + i];
    __syncthreads();
    float acc = bb1[t];
#pragma unroll 8
    for (int k = 0; k < LL * HH; k++) acc = fmaf(grow[k], w1[(size_t)t * (LL * HH) + k], acc);
    hbuf[t] = fmaxf(acc, 0.f);
    __syncthreads();
    if (t < CC) {
        float a = bb2[t];
#pragma unroll 8
        for (int k = 0; k < HH; k++) a = fmaf(hbuf[k], w2[t * HH + k], a);
        obuf[t] = a;
    }
    __syncthreads();
    if (t == 0) {
        float m = obuf[0];
#pragma unroll
        for (int j = 1; j < CC; j++) m = fmaxf(m, obuf[j]);
        float se = 0.f;
#pragma unroll
        for (int j = 0; j < CC; j++) se += expf(obuf[j] - m);
        float lse = m + logf(se);
#pragma unroll
        for (int j = 0; j < CC; j++) out[g * CC + j] = obuf[j] - lse;
    }
}

// ---------------- launcher ----------------
extern "C" void kernel_launch(void* const* d_in, const int* in_sizes, int n_in,
                              void* d_out, int out_size) {
    const float* x     = (const float*)d_in[0];
    const int*   ei    = (const int*)d_in[1];
    const int*   n2s   = (const int*)d_in[2];
    const int*   s2g   = (const int*)d_in[3];
    const float* W1    = (const float*)d_in[4];
    const float* b1    = (const float*)d_in[5];
    const float* g1    = (const float*)d_in[6];
    const float* be1   = (const float*)d_in[7];
    const float* W2    = (const float*)d_in[8];
    const float* b2    = (const float*)d_in[9];
    const float* g2    = (const float*)d_in[10];
    const float* be2   = (const float*)d_in[11];
    const float* eps   = (const float*)d_in[12];
    const float* lin1W = (const float*)d_in[13];
    const float* lin1b = (const float*)d_in[14];
    const float* lin2W = (const float*)d_in[15];
    const float* lin2b = (const float*)d_in[16];
    float* out = (float*)d_out;

    void* p;
    cudaGetSymbolAddress(&p, d_ubf);    __nv_bfloat16* ubfp   = (__nv_bfloat16*)p;
    cudaGetSymbolAddress(&p, d_tbf);    __nv_bfloat16* tbfp   = (__nv_bfloat16*)p;
    cudaGetSymbolAddress(&p, d_xbf);    __nv_bfloat16* xbfp   = (__nv_bfloat16*)p;
    cudaGetSymbolAddress(&p, d_featbf); __nv_bfloat16* featp  = (__nv_bfloat16*)p;
    cudaGetSymbolAddress(&p, d_statsA); float* statsp  = (float*)p;
    cudaGetSymbolAddress(&p, d_sub);    float* subp    = (float*)p;
    cudaGetSymbolAddress(&p, d_gph);    float* gphp    = (float*)p;
    cudaGetSymbolAddress(&p, d_suboff); int* suboffp   = (int*)p;
    cudaGetSymbolAddress(&p, d_gphoff); int* gphoffp   = (int*)p;
    cudaGetSymbolAddress(&p, d_Wbf);    __nv_bfloat16* wbfp = (__nv_bfloat16*)p;

    cudaFuncSetAttribute((const void*)mm_hmma_kernel<false>,
                         cudaFuncAttributeMaxDynamicSharedMemorySize, MM_SMEM);
    cudaFuncSetAttribute((const void*)mm_hmma_kernel<true>,
                         cudaFuncAttributeMaxDynamicSharedMemorySize, MM_SMEM);

    const int* src = ei;
    const int* dst = ei + EE;

    init_kernel<<<(NN * 32 + 255) / 256, 256>>>(x, W1, W2);

    count_kernel<<<(EE + 255) / 256, 256>>>(dst);
    scan1_kernel<<<SCAN_NB, 1024>>>();
    scan2_kernel<<<SCAN_NB, 1024>>>();
    fill_kernel<<<(EE + 255) / 256, 256>>>(src, dst);

    const int agg_blocks = (NN + 15) / 16;
    for (int l = 0; l < LL; l++) {
        const __nv_bfloat16* w1bf = wbfp + (size_t)(l * 2) * 16384;
        const __nv_bfloat16* w2bf = wbfp + (size_t)(l * 2 + 1) * 16384;
        float* st1 = statsp + (size_t)(2 * l) * 256;
        float* st2 = statsp + (size_t)(2 * l + 1) * 256;

        if (l == 0) {
            agg_kernel<false><<<agg_blocks, 256>>>(
                xbfp, FF, nullptr, nullptr, nullptr, eps, 0, ubfp);
        } else {
            agg_kernel<true><<<agg_blocks, 256>>>(
                featp + (size_t)(l - 1) * HH, LL * HH,
                statsp + (size_t)(2 * (l - 1) + 1) * 256,
                g2 + (size_t)(l - 1) * HH, be2 + (size_t)(l - 1) * HH, eps, l, ubfp);
        }

        mm_hmma_kernel<false><<<MMGRID, 256, MM_SMEM>>>(
            ubfp, HH, nullptr, nullptr, nullptr, w1bf,
            b1 + (size_t)l * HH, st1, tbfp, HH);

        mm_hmma_kernel<true><<<MMGRID, 256, MM_SMEM>>>(
            tbfp, HH, st1, g1 + (size_t)l * HH, be1 + (size_t)l * HH,
            w2bf, b2 + (size_t)l * HH, st2,
            featp + (size_t)l * HH, LL * HH);
    }

    offsets_kernel<<<(SS + GG + 2 + 255) / 256, 256>>>(n2s, s2g);
    segmean1_kernel<<<SS, 128>>>(featp, suboffp, subp, statsp, g2, be2);
    segmean2_kernel<<<GG, 128>>>(subp, gphoffp, gphp);

    head_kernel<<<GG, 128>>>(gphp, lin1W, lin1b, lin2W, lin2b, out);
}

// round 15
// speedup vs baseline: 1.1619x; 1.0029x over previous
#include <cuda_runtime.h>
#include <cuda_bf16.h>
#include <cstdint>
#include <cstddef>

#define NN 100000
#define EE 1600000
#define FF 128
#define HH 128
#define LL 4
#define SS 10000
#define GG 256
#define CC 10
#define SCAN_NB 98
#define NTILES 782
#define MMGRID 148

// ---------------- scratch (device globals; no allocation allowed) ----------------
__device__ int   d_deg[NN];          // zero at module load; re-zeroed in scan1 each run
__device__ int   d_off[NN + 1];
__device__ int   d_cursor[NN];
__device__ int   d_csr[EE];
__device__ int   d_bsum[SCAN_NB];
__device__ __nv_bfloat16 d_ubf[(size_t)NN * HH];
__device__ __nv_bfloat16 d_tbf[(size_t)NN * HH];
__device__ __nv_bfloat16 d_xbf[(size_t)NN * FF];
__device__ __nv_bfloat16 d_featbf[(size_t)NN * LL * HH];
__device__ float d_statsA[8 * 256];
__device__ int   d_suboff[SS + 1];
__device__ int   d_gphoff[GG + 1];
__device__ float d_sub[(size_t)SS * LL * HH];
__device__ __nv_bfloat16 d_Wbf[8 * 128 * 128];

// ---------------- smem layout for persistent mm kernel ----------------
#define SM_BIAS  0
#define SM_SSC   512
#define SM_SSH   1024
#define SM_STATS 1536
#define SM_WH    2560
#define SM_STG0  (SM_WH + 34816)      // 37376
#define STGB     34816                // 128 rows * 272B (bf16 stage)
#define SM_STG1  (SM_STG0 + STGB)     // 72192
#define MM_SMEM  (SM_STG1 + STGB)     // 107008

__device__ __forceinline__ uint32_t smem_u32(const void* p) {
    uint32_t a;
    asm("{ .reg .u64 t; cvta.to.shared.u64 t, %1; cvt.u32.u64 %0, t; }" : "=r"(a) : "l"(p));
    return a;
}
__device__ __forceinline__ void ldsm_x2(uint32_t* b, uint32_t addr) {
    asm volatile("ldmatrix.sync.aligned.m8n8.x2.shared.b16 {%0,%1}, [%2];"
        : "=r"(b[0]), "=r"(b[1]) : "r"(addr));
}
__device__ __forceinline__ void mma_bf16(float* c, const uint32_t* a, const uint32_t* b) {
    asm volatile("mma.sync.aligned.m16n8k16.row.col.f32.bf16.bf16.f32 "
        "{%0,%1,%2,%3}, {%4,%5,%6,%7}, {%8,%9}, {%0,%1,%2,%3};"
        : "+f"(c[0]), "+f"(c[1]), "+f"(c[2]), "+f"(c[3])
        : "r"(a[0]), "r"(a[1]), "r"(a[2]), "r"(a[3]), "r"(b[0]), "r"(b[1]));
}
__device__ __forceinline__ void cpasync16(uint32_t dst, const void* src, int sz) {
    asm volatile("cp.async.ca.shared.global [%0], [%1], 16, %2;"
        :: "r"(dst), "l"(src), "r"(sz) : "memory");
}
#define CP_COMMIT() asm volatile("cp.async.commit_group;" ::: "memory")
#define CP_WAIT0()  asm volatile("cp.async.wait_group 0;" ::: "memory")

__device__ __forceinline__ uint32_t pack_bf2(float2 v) {
    __nv_bfloat162 h = __floats2bfloat162_rn(v.x, v.y);
    return *reinterpret_cast<uint32_t*>(&h);
}
__device__ __forceinline__ float2 unpack_bf2(uint32_t w) {
    return make_float2(__uint_as_float(w << 16), __uint_as_float(w & 0xFFFF0000u));
}
__device__ __forceinline__ float4 bf4_to_f4(uint2 w) {
    float2 f0 = unpack_bf2(w.x);
    float2 f1 = unpack_bf2(w.y);
    return make_float4(f0.x, f0.y, f1.x, f1.y);
}
__device__ __forceinline__ uint32_t act_bf2(uint32_t w, float2 sc, float2 sh) {
    float2 v = unpack_bf2(w);
    v.x = fmaxf(fmaf(v.x, sc.x, sh.x), 0.f);
    v.y = fmaxf(fmaf(v.y, sc.y, sh.y), 0.f);
    return pack_bf2(v);
}

template <bool HAS_T>
__device__ __forceinline__ float4 act4(float4 v, float4 sc, float4 sh) {
    if (HAS_T) {
        v.x = fmaxf(fmaf(v.x, sc.x, sh.x), 0.f);
        v.y = fmaxf(fmaf(v.y, sc.y, sh.y), 0.f);
        v.z = fmaxf(fmaf(v.z, sc.z, sh.z), 0.f);
        v.w = fmaxf(fmaf(v.w, sc.w, sh.w), 0.f);
    }
    return v;
}

__device__ __forceinline__ void bn_from_stats(const float* st, const float* gamma,
                                              const float* beta, int c,
                                              float& sc, float& sh) {
    const float inv_n = 1.0f / (float)NN;
    float mu = st[c] * inv_n;
    float var = fmaf(-mu, mu, st[HH + c] * inv_n);
    float rinv = rsqrtf(var + 1e-5f);
    sc = rinv * gamma[c];
    sh = fmaf(-mu, sc, beta[c]);
}

__device__ __forceinline__ void mm_issue_copy(const __nv_bfloat16* __restrict__ Ain, int lda,
                                              uint32_t sb, int tile, int buf, int tid) {
    uint32_t base = sb + SM_STG0 + (uint32_t)buf * STGB;
    int row0 = tile * 128;
#pragma unroll
    for (int j = 0; j < 8; j++) {
        int c = tid + 256 * j;
        int r = c >> 4, ch = c & 15;
        int gr = row0 + r;
        uint32_t dst = base + (uint32_t)(r * 272 + ch * 16);
        int ok = (gr < NN) ? 16 : 0;
        const __nv_bfloat16* src = Ain + (size_t)(gr < NN ? gr : 0) * lda + ch * 8;
        cpasync16(dst, src, ok);
    }
}

// ---------------- init: x->bf16 + W->bf16 + zero stats + edge count (deg pre-zeroed) ----------------
__global__ void init_kernel(const float* __restrict__ x,
                            const float* __restrict__ W1, const float* __restrict__ W2,
                            const int* __restrict__ dst) {
    int i = blockIdx.x * blockDim.x + threadIdx.x;
    if (i < NN * 32) {
        float4 v = *(const float4*)&x[(size_t)i * 4];
        uint2 o;
        o.x = pack_bf2(make_float2(v.x, v.y));
        o.y = pack_bf2(make_float2(v.z, v.w));
        *(uint2*)&d_xbf[(size_t)i * 4] = o;
    }
    if (i < 8 * 256) d_statsA[i] = 0.f;
    if (i < 8 * 16384) {
        int mat = i >> 14, e = i & 16383, l = mat >> 1;
        float v = (mat & 1) ? W2[(size_t)l * 16384 + e] : W1[(size_t)l * 16384 + e];
        d_Wbf[i] = __float2bfloat16(v);
    }
    if (i < EE) atomicAdd(&d_deg[dst[i]], 1);
}

// ---------------- aggregation: 2 nodes/warp, 16B/lane gathers, index prefetch ----------------
template <bool HAS_T>
__global__ void agg_kernel(const __nv_bfloat16* __restrict__ xin, int ldx,
                           const float* __restrict__ stats_in,
                           const float* __restrict__ gamma, const float* __restrict__ beta,
                           const float* __restrict__ eps_ptr, int layer,
                           __nv_bfloat16* __restrict__ u) {
    __shared__ float ssc[HH], ssh[HH];
    int tid = threadIdx.x;
    if (HAS_T) {
        if (tid < HH) bn_from_stats(stats_in, gamma, beta, tid, ssc[tid], ssh[tid]);
        __syncthreads();
    }
    int wid = tid >> 5, lane = tid & 31;
    int half = lane >> 4, hl = lane & 15;
    int node = blockIdx.x * 16 + wid * 2 + half;
    if (node >= NN) return;
    float e = 1.0f + eps_ptr[layer];
    int c0 = hl * 8;
    float sc[8], sh[8];
    if (HAS_T) {
#pragma unroll
        for (int q = 0; q < 8; q++) { sc[q] = ssc[c0 + q]; sh[q] = ssh[c0 + q]; }
    }
    int s = d_off[node], epos = d_off[node + 1];
    float acc[8];
#pragma unroll
    for (int q = 0; q < 8; q++) acc[q] = 0.f;

    int j = s;
    if (j + 8 <= epos) {
        int ii[8];
#pragma unroll
        for (int q = 0; q < 8; q++) ii[q] = d_csr[j + q];
#pragma unroll 1
        while (true) {
            uint4 w[8];
#pragma unroll
            for (int q = 0; q < 8; q++)
                w[q] = *(const uint4*)&xin[(size_t)ii[q] * ldx + c0];
            int nj = j + 8;
            bool more = (nj + 8 <= epos);
            if (more) {
#pragma unroll
                for (int q = 0; q < 8; q++) ii[q] = d_csr[nj + q];
            }
#pragma unroll
            for (int q = 0; q < 8; q++) {
                const uint32_t* ww = (const uint32_t*)&w[q];
#pragma unroll
                for (int k = 0; k < 4; k++) {
                    float2 v = unpack_bf2(ww[k]);
                    if (HAS_T) {
                        v.x = fmaxf(fmaf(v.x, sc[2 * k], sh[2 * k]), 0.f);
                        v.y = fmaxf(fmaf(v.y, sc[2 * k + 1], sh[2 * k + 1]), 0.f);
                    }
                    acc[2 * k] += v.x;
                    acc[2 * k + 1] += v.y;
                }
            }
            j = nj;
            if (!more) break;
        }
    }
#pragma unroll 1
    for (; j < epos; ++j) {
        int i0 = d_csr[j];
        uint4 w0 = *(const uint4*)&xin[(size_t)i0 * ldx + c0];
        const uint32_t* ww = (const uint32_t*)&w0;
#pragma unroll
        for (int k = 0; k < 4; k++) {
            float2 v = unpack_bf2(ww[k]);
            if (HAS_T) {
                v.x = fmaxf(fmaf(v.x, sc[2 * k], sh[2 * k]), 0.f);
                v.y = fmaxf(fmaf(v.y, sc[2 * k + 1], sh[2 * k + 1]), 0.f);
            }
            acc[2 * k] += v.x;
            acc[2 * k + 1] += v.y;
        }
    }
    // self term
    {
        uint4 w0 = *(const uint4*)&xin[(size_t)node * ldx + c0];
        const uint32_t* ww = (const uint32_t*)&w0;
#pragma unroll
        for (int k = 0; k < 4; k++) {
            float2 v = unpack_bf2(ww[k]);
            if (HAS_T) {
                v.x = fmaxf(fmaf(v.x, sc[2 * k], sh[2 * k]), 0.f);
                v.y = fmaxf(fmaf(v.y, sc[2 * k + 1], sh[2 * k + 1]), 0.f);
            }
            acc[2 * k] = fmaf(e, v.x, acc[2 * k]);
            acc[2 * k + 1] = fmaf(e, v.y, acc[2 * k + 1]);
        }
    }
    uint4 o;
    uint32_t* oo = (uint32_t*)&o;
#pragma unroll
    for (int k = 0; k < 4; k++)
        oo[k] = pack_bf2(make_float2(acc[2 * k], acc[2 * k + 1]));
    *(uint4*)&u[(size_t)node * HH + c0] = o;
}

// ---------------- persistent pipelined GEMM (R11/R14 structure, verbatim) ----------------
template <bool HAS_T>
__global__ void __launch_bounds__(256, 1)
mm_hmma_kernel(const __nv_bfloat16* __restrict__ Ain, int lda,
               const float* __restrict__ stats_in,
               const float* __restrict__ gamma, const float* __restrict__ beta,
               const __nv_bfloat16* __restrict__ Wbf,
               const float* __restrict__ bias,
               float* __restrict__ stats_out,
               __nv_bfloat16* __restrict__ Y, int ldy) {
    extern __shared__ char smem[];
    uint32_t sb = smem_u32(smem);
    int tid = threadIdx.x, wid = tid >> 5, lane = tid & 31;
    int gid = lane >> 2, ctib = lane & 3;
    float* sbias = (float*)(smem + SM_BIAS);
    float* ssc   = (float*)(smem + SM_SSC);
    float* ssh   = (float*)(smem + SM_SSH);
    float* sstat = (float*)(smem + SM_STATS);

    if (tid < 128) {
        sbias[tid] = bias[tid];
        if (HAS_T) bn_from_stats(stats_in, gamma, beta, tid, ssc[tid], ssh[tid]);
    }
    sstat[tid] = 0.f;

#pragma unroll
    for (int i = tid; i < 128 * 16; i += 256) {
        int r = i >> 4, c8 = (i & 15) * 8;
        uint32_t dsto = (uint32_t)(r * 272 + c8 * 2);
        *(uint4*)(smem + SM_WH + dsto) = *(const uint4*)&Wbf[r * 128 + c8];
    }

    mm_issue_copy(Ain, lda, sb, blockIdx.x, 0, tid);
    CP_COMMIT();

    float sA[16], sB[16], qA[16], qB[16];
#pragma unroll
    for (int nt = 0; nt < 16; nt++) { sA[nt] = 0.f; sB[nt] = 0.f; qA[nt] = 0.f; qB[nt] = 0.f; }

    int p = 0;
    int r0w = 16 * wid + gid;
#pragma unroll 1
    for (int tile = blockIdx.x; tile < NTILES; tile += MMGRID) {
        CP_WAIT0();
        __syncthreads();

        const char* stg = smem + SM_STG0 + (uint32_t)p * STGB;
        uint32_t ah[32];
#pragma unroll
        for (int k8 = 0; k8 < 8; k8++) {
            uint32_t co = (uint32_t)(k8 * 32 + ctib * 4);
            uint32_t w00 = *(const uint32_t*)(stg + r0w * 272 + co);
            uint32_t w10 = *(const uint32_t*)(stg + (r0w + 8) * 272 + co);
            uint32_t w01 = *(const uint32_t*)(stg + r0w * 272 + co + 16);
            uint32_t w11 = *(const uint32_t*)(stg + (r0w + 8) * 272 + co + 16);
            if (HAS_T) {
                int cc = k8 * 16 + 2 * ctib;
                float2 sa = *(const float2*)&ssc[cc],     ha = *(const float2*)&ssh[cc];
                float2 sc = *(const float2*)&ssc[cc + 8], hc = *(const float2*)&ssh[cc + 8];
                w00 = act_bf2(w00, sa, ha);
                w10 = act_bf2(w10, sa, ha);
                w01 = act_bf2(w01, sc, hc);
                w11 = act_bf2(w11, sc, hc);
            }
            ah[k8 * 4 + 0] = w00;
            ah[k8 * 4 + 1] = w10;
            ah[k8 * 4 + 2] = w01;
            ah[k8 * 4 + 3] = w11;
        }
        __syncthreads();

        int nxt = tile + MMGRID;
        if (nxt < NTILES) mm_issue_copy(Ain, lda, sb, nxt, 1 - p, tid);
        CP_COMMIT();

        int row0 = tile * 128;
        int g = lane & 7, q = (lane >> 3) & 1;
        uint32_t wbase = sb + SM_WH + (uint32_t)(g * 272 + q * 16);
#pragma unroll
        for (int nt = 0; nt < 16; nt++) {
            float ca[4] = {0.f, 0.f, 0.f, 0.f};
            float cb[4] = {0.f, 0.f, 0.f, 0.f};
#pragma unroll
            for (int k8 = 0; k8 < 4; k8++) {
                uint32_t wa = wbase + (uint32_t)(nt * 8 * 272 + k8 * 32);
                uint32_t bh[2], bh2[2];
                ldsm_x2(bh, wa);
                ldsm_x2(bh2, wa + 4 * 32);
                mma_bf16(ca, &ah[k8 * 4], bh);
                mma_bf16(cb, &ah[(k8 + 4) * 4], bh2);
            }
            int col = nt * 8 + 2 * ctib;
            float bx = sbias[col], by = sbias[col + 1];
            float v0 = ca[0] + cb[0] + bx;
            float v1 = ca[1] + cb[1] + by;
            float v2 = ca[2] + cb[2] + bx;
            float v3 = ca[3] + cb[3] + by;
            int gr0 = row0 + r0w, gr1 = gr0 + 8;
            if (gr0 < NN)
                *(uint32_t*)&Y[(size_t)gr0 * ldy + col] = pack_bf2(make_float2(v0, v1));
            else { v0 = 0.f; v1 = 0.f; }
            if (gr1 < NN)
                *(uint32_t*)&Y[(size_t)gr1 * ldy + col] = pack_bf2(make_float2(v2, v3));
            else { v2 = 0.f; v3 = 0.f; }
            sA[nt] += v0 + v2;
            sB[nt] += v1 + v3;
            qA[nt] = fmaf(v0, v0, fmaf(v2, v2, qA[nt]));
            qB[nt] = fmaf(v1, v1, fmaf(v3, v3, qB[nt]));
        }
        p ^= 1;
    }

#pragma unroll
    for (int nt = 0; nt < 16; nt++) {
        float s0 = sA[nt], s1 = sB[nt], q0 = qA[nt], q1 = qB[nt];
#pragma unroll
        for (int h = 4; h < 32; h <<= 1) {
            s0 += __shfl_xor_sync(0xffffffffu, s0, h);
            s1 += __shfl_xor_sync(0xffffffffu, s1, h);
            q0 += __shfl_xor_sync(0xffffffffu, q0, h);
            q1 += __shfl_xor_sync(0xffffffffu, q1, h);
        }
        if (lane < 4) {
            int col = nt * 8 + 2 * lane;
            atomicAdd(&sstat[col], s0);
            atomicAdd(&sstat[col + 1], s1);
            atomicAdd(&sstat[128 + col], q0);
            atomicAdd(&sstat[128 + col + 1], q1);
        }
    }
    __syncthreads();
    atomicAdd(&stats_out[tid], sstat[tid]);
}

// ---------------- CSR scan (deg re-zeroed here for the next replay) ----------------
__global__ void scan1_kernel() {
    __shared__ int wsum[32];
    int t = threadIdx.x, lane = t & 31, w = t >> 5;
    int idx = blockIdx.x * 1024 + t;
    int v = 0;
    if (idx < NN) {
        v = d_deg[idx];
        d_deg[idx] = 0;   // reset for next graph replay
    }
    int x = v;
#pragma unroll
    for (int d = 1; d < 32; d <<= 1) {
        int y = __shfl_up_sync(0xffffffffu, x, d);
        if (lane >= d) x += y;
    }
    if (lane == 31) wsum[w] = x;
    __syncthreads();
    if (w == 0) {
        int s = wsum[lane];
#pragma unroll
        for (int d = 1; d < 32; d <<= 1) {
            int y = __shfl_up_sync(0xffffffffu, s, d);
            if (lane >= d) s += y;
        }
        wsum[lane] = s;
    }
    __syncthreads();
    int woff = (w > 0) ? wsum[w - 1] : 0;
    int excl = woff + x - v;
    if (idx < NN) d_off[idx] = excl;
    if (t == 1023) d_bsum[blockIdx.x] = woff + x;
}

__global__ void scan2_kernel() {
    __shared__ int bs[SCAN_NB];
    __shared__ int boff_s;
    int t = threadIdx.x;
    if (t < SCAN_NB) bs[t] = d_bsum[t];
    __syncthreads();
    if (t == 0) {
        int acc = 0;
#pragma unroll 1
        for (int b = 0; b < (int)blockIdx.x; b++) acc += bs[b];
        boff_s = acc;
        if (blockIdx.x == SCAN_NB - 1) {
            int tot = acc;
            for (int b = blockIdx.x; b < SCAN_NB; b++) tot += bs[b];
            d_off[NN] = tot;
        }
    }
    __syncthreads();
    int boff = boff_s;
    int idx = blockIdx.x * 1024 + t;
    if (idx < NN) {
        int val = d_off[idx] + boff;
        d_off[idx] = val;
        d_cursor[idx] = val;
    }
}

__global__ void fill_kernel(const int* __restrict__ src, const int* __restrict__ dst) {
    int i = blockIdx.x * blockDim.x + threadIdx.x;
    if (i < EE) {
        int p = atomicAdd(&d_cursor[dst[i]], 1);
        d_csr[p] = src[i];
    }
}

// ---------------- pooling offsets (both levels in one launch) ----------------
__global__ void offsets_kernel(const int* __restrict__ n2s, const int* __restrict__ s2g) {
    int i = blockIdx.x * blockDim.x + threadIdx.x;
    if (i <= SS) {
        int lo = 0, hi = NN;
        while (lo < hi) {
            int mid = (lo + hi) >> 1;
            if (n2s[mid] < i) lo = mid + 1; else hi = mid;
        }
        d_suboff[i] = lo;
    }
    int g = i - (SS + 1);
    if (g >= 0 && g <= GG) {
        int lo = 0, hi = SS;
        while (lo < hi) {
            int mid = (lo + hi) >> 1;
            if (s2g[mid] < g) lo = mid + 1; else hi = mid;
        }
        d_gphoff[g] = lo;
    }
}

__global__ void segmean1_kernel(const __nv_bfloat16* __restrict__ in, const int* __restrict__ off,
                                float* __restrict__ out,
                                const float* __restrict__ statsA,
                                const float* __restrict__ g2, const float* __restrict__ be2) {
    int s = blockIdx.x, t = threadIdx.x;
    int lt = t >> 5;
    int c0 = (t & 31) * 4;
    const float* st = statsA + (size_t)(2 * lt + 1) * 256;
    float4 sc4, sh4;
    {
        float sc, sh;
        bn_from_stats(st, g2 + lt * HH, be2 + lt * HH, c0 + 0, sc, sh); sc4.x = sc; sh4.x = sh;
        bn_from_stats(st, g2 + lt * HH, be2 + lt * HH, c0 + 1, sc, sh); sc4.y = sc; sh4.y = sh;
        bn_from_stats(st, g2 + lt * HH, be2 + lt * HH, c0 + 2, sc, sh); sc4.z = sc; sh4.z = sh;
        bn_from_stats(st, g2 + lt * HH, be2 + lt * HH, c0 + 3, sc, sh); sc4.w = sc; sh4.w = sh;
    }
    int r0 = off[s], r1 = off[s + 1];
    float4 acc = make_float4(0.f, 0.f, 0.f, 0.f);
    for (int r = r0; r < r1; r++) {
        float4 v = bf4_to_f4(*(const uint2*)&in[(size_t)r * (LL * HH) + t * 4]);
        v = act4<true>(v, sc4, sh4);
        acc.x += v.x; acc.y += v.y; acc.z += v.z; acc.w += v.w;
    }
    float inv = 1.0f / fmaxf((float)(r1 - r0), 1.0f);
    float4 o = make_float4(acc.x * inv, acc.y * inv, acc.z * inv, acc.w * inv);
    *(float4*)&out[(size_t)s * (LL * HH) + t * 4] = o;
}

// ---------------- fused graph-mean + head ----------------
__global__ void head_kernel(const float* __restrict__ sub, const int* __restrict__ goff,
                            const float* __restrict__ w1, const float* __restrict__ bb1,
                            const float* __restrict__ w2, const float* __restrict__ bb2,
                            float* __restrict__ out) {
    __shared__ float grow[LL * HH];
    __shared__ float hbuf[HH];
    __shared__ float obuf[CC];
    int g = blockIdx.x, t = threadIdx.x;
    // graph mean over subgraph rows (each thread covers 4 cols)
    {
        int r0 = goff[g], r1 = goff[g + 1];
        float4 acc = make_float4(0.f, 0.f, 0.f, 0.f);
        for (int r = r0; r < r1; r++) {
            float4 v = *(const float4*)&sub[(size_t)r * (LL * HH) + t * 4];
            acc.x += v.x; acc.y += v.y; acc.z += v.z; acc.w += v.w;
        }
        float inv = 1.0f / fmaxf((float)(r1 - r0), 1.0f);
        *(float4*)&grow[t * 4] = make_float4(acc.x * inv, acc.y * inv, acc.z * inv, acc.w * inv);
    }
    __syncthreads();
    float acc = bb1[t];
#pragma unroll 8
    for (int k = 0; k < LL * HH; k++) acc = fmaf(grow[k], w1[(size_t)t * (LL * HH) + k], acc);
    hbuf[t] = fmaxf(acc, 0.f);
    __syncthreads();
    if (t < CC) {
        float a = bb2[t];
#pragma unroll 8
        for (int k = 0; k < HH; k++) a = fmaf(hbuf[k], w2[t * HH + k], a);
        obuf[t] = a;
    }
    __syncthreads();
    if (t == 0) {
        float m = obuf[0];
#pragma unroll
        for (int j = 1; j < CC; j++) m = fmaxf(m, obuf[j]);
        float se = 0.f;
#pragma unroll
        for (int j = 0; j < CC; j++) se += expf(obuf[j] - m);
        float lse = m + logf(se);
#pragma unroll
        for (int j = 0; j < CC; j++) out[g * CC + j] = obuf[j] - lse;
    }
}

// ---------------- launcher ----------------
extern "C" void kernel_launch(void* const* d_in, const int* in_sizes, int n_in,
                              void* d_out, int out_size) {
    const float* x     = (const float*)d_in[0];
    const int*   ei    = (const int*)d_in[1];
    const int*   n2s   = (const int*)d_in[2];
    const int*   s2g   = (const int*)d_in[3];
    const float* W1    = (const float*)d_in[4];
    const float* b1    = (const float*)d_in[5];
    const float* g1    = (const float*)d_in[6];
    const float* be1   = (const float*)d_in[7];
    const float* W2    = (const float*)d_in[8];
    const float* b2    = (const float*)d_in[9];
    const float* g2    = (const float*)d_in[10];
    const float* be2   = (const float*)d_in[11];
    const float* eps   = (const float*)d_in[12];
    const float* lin1W = (const float*)d_in[13];
    const float* lin1b = (const float*)d_in[14];
    const float* lin2W = (const float*)d_in[15];
    const float* lin2b = (const float*)d_in[16];
    float* out = (float*)d_out;

    void* p;
    cudaGetSymbolAddress(&p, d_ubf);    __nv_bfloat16* ubfp   = (__nv_bfloat16*)p;
    cudaGetSymbolAddress(&p, d_tbf);    __nv_bfloat16* tbfp   = (__nv_bfloat16*)p;
    cudaGetSymbolAddress(&p, d_xbf);    __nv_bfloat16* xbfp   = (__nv_bfloat16*)p;
    cudaGetSymbolAddress(&p, d_featbf); __nv_bfloat16* featp  = (__nv_bfloat16*)p;
    cudaGetSymbolAddress(&p, d_statsA); float* statsp  = (float*)p;
    cudaGetSymbolAddress(&p, d_sub);    float* subp    = (float*)p;
    cudaGetSymbolAddress(&p, d_suboff); int* suboffp   = (int*)p;
    cudaGetSymbolAddress(&p, d_gphoff); int* gphoffp   = (int*)p;
    cudaGetSymbolAddress(&p, d_Wbf);    __nv_bfloat16* wbfp = (__nv_bfloat16*)p;

    cudaFuncSetAttribute((const void*)mm_hmma_kernel<false>,
                         cudaFuncAttributeMaxDynamicSharedMemorySize, MM_SMEM);
    cudaFuncSetAttribute((const void*)mm_hmma_kernel<true>,
                         cudaFuncAttributeMaxDynamicSharedMemorySize, MM_SMEM);

    const int* src = ei;
    const int* dst = ei + EE;

    init_kernel<<<(NN * 32 + 255) / 256, 256>>>(x, W1, W2, dst);
    scan1_kernel<<<SCAN_NB, 1024>>>();
    scan2_kernel<<<SCAN_NB, 1024>>>();
    fill_kernel<<<(EE + 255) / 256, 256>>>(src, dst);

    const int agg_blocks = (NN + 15) / 16;
    for (int l = 0; l < LL; l++) {
        const __nv_bfloat16* w1bf = wbfp + (size_t)(l * 2) * 16384;
        const __nv_bfloat16* w2bf = wbfp + (size_t)(l * 2 + 1) * 16384;
        float* st1 = statsp + (size_t)(2 * l) * 256;
        float* st2 = statsp + (size_t)(2 * l + 1) * 256;

        if (l == 0) {
            agg_kernel<false><<<agg_blocks, 256>>>(
                xbfp, FF, nullptr, nullptr, nullptr, eps, 0, ubfp);
        } else {
            agg_kernel<true><<<agg_blocks, 256>>>(
                featp + (size_t)(l - 1) * HH, LL * HH,
                statsp + (size_t)(2 * (l - 1) + 1) * 256,
                g2 + (size_t)(l - 1) * HH, be2 + (size_t)(l - 1) * HH, eps, l, ubfp);
        }

        mm_hmma_kernel<false><<<MMGRID, 256, MM_SMEM>>>(
            ubfp, HH, nullptr, nullptr, nullptr, w1bf,
            b1 + (size_t)l * HH, st1, tbfp, HH);

        mm_hmma_kernel<true><<<MMGRID, 256, MM_SMEM>>>(
            tbfp, HH, st1, g1 + (size_t)l * HH, be1 + (size_t)l * HH,
            w2bf, b2 + (size_t)l * HH, st2,
            featp + (size_t)l * HH, LL * HH);
    }

    offsets_kernel<<<(SS + GG + 2 + 255) / 256, 256>>>(n2s, s2g);
    segmean1_kernel<<<SS, 128>>>(featp, suboffp, subp, statsp, g2, be2);
    head_kernel<<<GG, 128>>>(subp, gphoffp, lin1W, lin1b, lin2W, lin2b, out);
}

// round 16
// speedup vs baseline: 1.2733x; 1.0958x over previous
#include <cuda_runtime.h>
#include <cuda_bf16.h>
#include <cstdint>
#include <cstddef>

#define NN 100000
#define EE 1600000
#define FF 128
#define HH 128
#define LL 4
#define SS 10000
#define GG 256
#define CC 10
#define SCAN_NB 98
#define NTILES 782
#define MMGRID 148

// ---------------- scratch (device globals; no allocation allowed) ----------------
__device__ int   d_deg[NN];          // zero at module load; re-zeroed in scan1 each run
__device__ int   d_off[NN + 1];
__device__ int   d_cursor[NN];
__device__ int   d_csr[EE];
__device__ int   d_bsum[SCAN_NB];
__device__ __nv_bfloat16 d_ubf[(size_t)NN * HH];
__device__ __nv_bfloat16 d_tbf[(size_t)NN * HH];
__device__ __nv_bfloat16 d_xbf[(size_t)NN * FF];
__device__ __nv_bfloat16 d_abf[(size_t)NN * HH];   // pre-activated act(feat[l-1]) (compact)
__device__ __nv_bfloat16 d_featbf[(size_t)NN * LL * HH];
__device__ float d_statsA[8 * 256];
__device__ int   d_suboff[SS + 1];
__device__ int   d_gphoff[GG + 1];
__device__ float d_sub[(size_t)SS * LL * HH];
__device__ __nv_bfloat16 d_Wbf[8 * 128 * 128];

// ---------------- smem layout for persistent mm kernel ----------------
#define SM_BIAS  0
#define SM_SSC   512
#define SM_SSH   1024
#define SM_STATS 1536
#define SM_WH    2560
#define SM_STG0  (SM_WH + 34816)      // 37376
#define STGB     34816                // 128 rows * 272B (bf16 stage)
#define SM_STG1  (SM_STG0 + STGB)     // 72192
#define MM_SMEM  (SM_STG1 + STGB)     // 107008

__device__ __forceinline__ uint32_t smem_u32(const void* p) {
    uint32_t a;
    asm("{ .reg .u64 t; cvta.to.shared.u64 t, %1; cvt.u32.u64 %0, t; }" : "=r"(a) : "l"(p));
    return a;
}
__device__ __forceinline__ void ldsm_x2(uint32_t* b, uint32_t addr) {
    asm volatile("ldmatrix.sync.aligned.m8n8.x2.shared.b16 {%0,%1}, [%2];"
        : "=r"(b[0]), "=r"(b[1]) : "r"(addr));
}
__device__ __forceinline__ void mma_bf16(float* c, const uint32_t* a, const uint32_t* b) {
    asm volatile("mma.sync.aligned.m16n8k16.row.col.f32.bf16.bf16.f32 "
        "{%0,%1,%2,%3}, {%4,%5,%6,%7}, {%8,%9}, {%0,%1,%2,%3};"
        : "+f"(c[0]), "+f"(c[1]), "+f"(c[2]), "+f"(c[3])
        : "r"(a[0]), "r"(a[1]), "r"(a[2]), "r"(a[3]), "r"(b[0]), "r"(b[1]));
}
__device__ __forceinline__ void cpasync16(uint32_t dst, const void* src, int sz) {
    asm volatile("cp.async.ca.shared.global [%0], [%1], 16, %2;"
        :: "r"(dst), "l"(src), "r"(sz) : "memory");
}
#define CP_COMMIT() asm volatile("cp.async.commit_group;" ::: "memory")
#define CP_WAIT0()  asm volatile("cp.async.wait_group 0;" ::: "memory")

__device__ __forceinline__ uint32_t pack_bf2(float2 v) {
    __nv_bfloat162 h = __floats2bfloat162_rn(v.x, v.y);
    return *reinterpret_cast<uint32_t*>(&h);
}
__device__ __forceinline__ float2 unpack_bf2(uint32_t w) {
    return make_float2(__uint_as_float(w << 16), __uint_as_float(w & 0xFFFF0000u));
}
__device__ __forceinline__ float4 bf4_to_f4(uint2 w) {
    float2 f0 = unpack_bf2(w.x);
    float2 f1 = unpack_bf2(w.y);
    return make_float4(f0.x, f0.y, f1.x, f1.y);
}
__device__ __forceinline__ uint32_t act_bf2(uint32_t w, float2 sc, float2 sh) {
    float2 v = unpack_bf2(w);
    v.x = fmaxf(fmaf(v.x, sc.x, sh.x), 0.f);
    v.y = fmaxf(fmaf(v.y, sc.y, sh.y), 0.f);
    return pack_bf2(v);
}

__device__ __forceinline__ float4 act4(float4 v, float4 sc, float4 sh) {
    v.x = fmaxf(fmaf(v.x, sc.x, sh.x), 0.f);
    v.y = fmaxf(fmaf(v.y, sc.y, sh.y), 0.f);
    v.z = fmaxf(fmaf(v.z, sc.z, sh.z), 0.f);
    v.w = fmaxf(fmaf(v.w, sc.w, sh.w), 0.f);
    return v;
}

__device__ __forceinline__ void bn_from_stats(const float* st, const float* gamma,
                                              const float* beta, int c,
                                              float& sc, float& sh) {
    const float inv_n = 1.0f / (float)NN;
    float mu = st[c] * inv_n;
    float var = fmaf(-mu, mu, st[HH + c] * inv_n);
    float rinv = rsqrtf(var + 1e-5f);
    sc = rinv * gamma[c];
    sh = fmaf(-mu, sc, beta[c]);
}

__device__ __forceinline__ void mm_issue_copy(const __nv_bfloat16* __restrict__ Ain, int lda,
                                              uint32_t sb, int tile, int buf, int tid) {
    uint32_t base = sb + SM_STG0 + (uint32_t)buf * STGB;
    int row0 = tile * 128;
#pragma unroll
    for (int j = 0; j < 8; j++) {
        int c = tid + 256 * j;
        int r = c >> 4, ch = c & 15;
        int gr = row0 + r;
        uint32_t dst = base + (uint32_t)(r * 272 + ch * 16);
        int ok = (gr < NN) ? 16 : 0;
        const __nv_bfloat16* src = Ain + (size_t)(gr < NN ? gr : 0) * lda + ch * 8;
        cpasync16(dst, src, ok);
    }
}

// ---------------- init: x->bf16 + W->bf16 + zero stats + edge count (deg pre-zeroed) ----------------
__global__ void init_kernel(const float* __restrict__ x,
                            const float* __restrict__ W1, const float* __restrict__ W2,
                            const int* __restrict__ dst) {
    int i = blockIdx.x * blockDim.x + threadIdx.x;
    if (i < NN * 32) {
        float4 v = *(const float4*)&x[(size_t)i * 4];
        uint2 o;
        o.x = pack_bf2(make_float2(v.x, v.y));
        o.y = pack_bf2(make_float2(v.z, v.w));
        *(uint2*)&d_xbf[(size_t)i * 4] = o;
    }
    if (i < 8 * 256) d_statsA[i] = 0.f;
    if (i < 8 * 16384) {
        int mat = i >> 14, e = i & 16383, l = mat >> 1;
        float v = (mat & 1) ? W2[(size_t)l * 16384 + e] : W1[(size_t)l * 16384 + e];
        d_Wbf[i] = __float2bfloat16(v);
    }
    if (i < EE) atomicAdd(&d_deg[dst[i]], 1);
}

// ---------------- act pass: d_abf = BN+ReLU(feat slot) (compact [NN,128] bf16) ----------------
__global__ void act_kernel(const __nv_bfloat16* __restrict__ in,   // feat slot base, ld = LL*HH
                           const float* __restrict__ st,
                           const float* __restrict__ gamma, const float* __restrict__ beta,
                           __nv_bfloat16* __restrict__ outp) {
    __shared__ float ssc[HH], ssh[HH];
    int tid = threadIdx.x;
    if (tid < HH) bn_from_stats(st, gamma, beta, tid, ssc[tid], ssh[tid]);
    __syncthreads();
    int stride = gridDim.x * blockDim.x;
#pragma unroll 1
    for (int i = blockIdx.x * blockDim.x + tid; i < NN * 32; i += stride) {
        int r = i >> 5, cp = i & 31;   // 32 uint2 (4 cols) per row
        uint2 w = *(const uint2*)&in[(size_t)r * (LL * HH) + cp * 4];
        float2 s0 = *(const float2*)&ssc[cp * 4],     h0 = *(const float2*)&ssh[cp * 4];
        float2 s1 = *(const float2*)&ssc[cp * 4 + 2], h1 = *(const float2*)&ssh[cp * 4 + 2];
        uint2 o;
        o.x = act_bf2(w.x, s0, h0);
        o.y = act_bf2(w.y, s1, h1);
        *(uint2*)&outp[(size_t)r * HH + cp * 4] = o;
    }
}

// ---------------- aggregation: 2 nodes/warp, 16B/lane gathers, pre-activated input ----------------
__global__ void agg_kernel(const __nv_bfloat16* __restrict__ xin,   // [NN,128] bf16, pre-activated
                           const float* __restrict__ eps_ptr, int layer,
                           __nv_bfloat16* __restrict__ u) {
    int tid = threadIdx.x;
    int wid = tid >> 5, lane = tid & 31;
    int half = lane >> 4, hl = lane & 15;
    int node = blockIdx.x * 16 + wid * 2 + half;
    if (node >= NN) return;
    float e = 1.0f + eps_ptr[layer];
    int c0 = hl * 8;
    int s = d_off[node], epos = d_off[node + 1];
    float acc[8];
#pragma unroll
    for (int q = 0; q < 8; q++) acc[q] = 0.f;

    int j = s;
    if (j + 8 <= epos) {
        int ii[8];
#pragma unroll
        for (int q = 0; q < 8; q++) ii[q] = d_csr[j + q];
#pragma unroll 1
        while (true) {
            uint4 w[8];
#pragma unroll
            for (int q = 0; q < 8; q++)
                w[q] = *(const uint4*)&xin[(size_t)ii[q] * HH + c0];
            int nj = j + 8;
            bool more = (nj + 8 <= epos);
            if (more) {
#pragma unroll
                for (int q = 0; q < 8; q++) ii[q] = d_csr[nj + q];
            }
#pragma unroll
            for (int q = 0; q < 8; q++) {
                const uint32_t* ww = (const uint32_t*)&w[q];
#pragma unroll
                for (int k = 0; k < 4; k++) {
                    float2 v = unpack_bf2(ww[k]);
                    acc[2 * k] += v.x;
                    acc[2 * k + 1] += v.y;
                }
            }
            j = nj;
            if (!more) break;
        }
    }
#pragma unroll 1
    for (; j < epos; ++j) {
        int i0 = d_csr[j];
        uint4 w0 = *(const uint4*)&xin[(size_t)i0 * HH + c0];
        const uint32_t* ww = (const uint32_t*)&w0;
#pragma unroll
        for (int k = 0; k < 4; k++) {
            float2 v = unpack_bf2(ww[k]);
            acc[2 * k] += v.x;
            acc[2 * k + 1] += v.y;
        }
    }
    // self term
    {
        uint4 w0 = *(const uint4*)&xin[(size_t)node * HH + c0];
        const uint32_t* ww = (const uint32_t*)&w0;
#pragma unroll
        for (int k = 0; k < 4; k++) {
            float2 v = unpack_bf2(ww[k]);
            acc[2 * k] = fmaf(e, v.x, acc[2 * k]);
            acc[2 * k + 1] = fmaf(e, v.y, acc[2 * k + 1]);
        }
    }
    uint4 o;
    uint32_t* oo = (uint32_t*)&o;
#pragma unroll
    for (int k = 0; k < 4; k++)
        oo[k] = pack_bf2(make_float2(acc[2 * k], acc[2 * k + 1]));
    *(uint4*)&u[(size_t)node * HH + c0] = o;
}

// ---------------- persistent pipelined GEMM (R11/R14 structure, verbatim) ----------------
template <bool HAS_T>
__global__ void __launch_bounds__(256, 1)
mm_hmma_kernel(const __nv_bfloat16* __restrict__ Ain, int lda,
               const float* __restrict__ stats_in,
               const float* __restrict__ gamma, const float* __restrict__ beta,
               const __nv_bfloat16* __restrict__ Wbf,
               const float* __restrict__ bias,
               float* __restrict__ stats_out,
               __nv_bfloat16* __restrict__ Y, int ldy) {
    extern __shared__ char smem[];
    uint32_t sb = smem_u32(smem);
    int tid = threadIdx.x, wid = tid >> 5, lane = tid & 31;
    int gid = lane >> 2, ctib = lane & 3;
    float* sbias = (float*)(smem + SM_BIAS);
    float* ssc   = (float*)(smem + SM_SSC);
    float* ssh   = (float*)(smem + SM_SSH);
    float* sstat = (float*)(smem + SM_STATS);

    if (tid < 128) {
        sbias[tid] = bias[tid];
        if (HAS_T) bn_from_stats(stats_in, gamma, beta, tid, ssc[tid], ssh[tid]);
    }
    sstat[tid] = 0.f;

#pragma unroll
    for (int i = tid; i < 128 * 16; i += 256) {
        int r = i >> 4, c8 = (i & 15) * 8;
        uint32_t dsto = (uint32_t)(r * 272 + c8 * 2);
        *(uint4*)(smem + SM_WH + dsto) = *(const uint4*)&Wbf[r * 128 + c8];
    }

    mm_issue_copy(Ain, lda, sb, blockIdx.x, 0, tid);
    CP_COMMIT();

    float sA[16], sB[16], qA[16], qB[16];
#pragma unroll
    for (int nt = 0; nt < 16; nt++) { sA[nt] = 0.f; sB[nt] = 0.f; qA[nt] = 0.f; qB[nt] = 0.f; }

    int p = 0;
    int r0w = 16 * wid + gid;
#pragma unroll 1
    for (int tile = blockIdx.x; tile < NTILES; tile += MMGRID) {
        CP_WAIT0();
        __syncthreads();

        const char* stg = smem + SM_STG0 + (uint32_t)p * STGB;
        uint32_t ah[32];
#pragma unroll
        for (int k8 = 0; k8 < 8; k8++) {
            uint32_t co = (uint32_t)(k8 * 32 + ctib * 4);
            uint32_t w00 = *(const uint32_t*)(stg + r0w * 272 + co);
            uint32_t w10 = *(const uint32_t*)(stg + (r0w + 8) * 272 + co);
            uint32_t w01 = *(const uint32_t*)(stg + r0w * 272 + co + 16);
            uint32_t w11 = *(const uint32_t*)(stg + (r0w + 8) * 272 + co + 16);
            if (HAS_T) {
                int cc = k8 * 16 + 2 * ctib;
                float2 sa = *(const float2*)&ssc[cc],     ha = *(const float2*)&ssh[cc];
                float2 sc = *(const float2*)&ssc[cc + 8], hc = *(const float2*)&ssh[cc + 8];
                w00 = act_bf2(w00, sa, ha);
                w10 = act_bf2(w10, sa, ha);
                w01 = act_bf2(w01, sc, hc);
                w11 = act_bf2(w11, sc, hc);
            }
            ah[k8 * 4 + 0] = w00;
            ah[k8 * 4 + 1] = w10;
            ah[k8 * 4 + 2] = w01;
            ah[k8 * 4 + 3] = w11;
        }
        __syncthreads();

        int nxt = tile + MMGRID;
        if (nxt < NTILES) mm_issue_copy(Ain, lda, sb, nxt, 1 - p, tid);
        CP_COMMIT();

        int row0 = tile * 128;
        int g = lane & 7, q = (lane >> 3) & 1;
        uint32_t wbase = sb + SM_WH + (uint32_t)(g * 272 + q * 16);
#pragma unroll
        for (int nt = 0; nt < 16; nt++) {
            float ca[4] = {0.f, 0.f, 0.f, 0.f};
            float cb[4] = {0.f, 0.f, 0.f, 0.f};
#pragma unroll
            for (int k8 = 0; k8 < 4; k8++) {
                uint32_t wa = wbase + (uint32_t)(nt * 8 * 272 + k8 * 32);
                uint32_t bh[2], bh2[2];
                ldsm_x2(bh, wa);
                ldsm_x2(bh2, wa + 4 * 32);
                mma_bf16(ca, &ah[k8 * 4], bh);
                mma_bf16(cb, &ah[(k8 + 4) * 4], bh2);
            }
            int col = nt * 8 + 2 * ctib;
            float bx = sbias[col], by = sbias[col + 1];
            float v0 = ca[0] + cb[0] + bx;
            float v1 = ca[1] + cb[1] + by;
            float v2 = ca[2] + cb[2] + bx;
            float v3 = ca[3] + cb[3] + by;
            int gr0 = row0 + r0w, gr1 = gr0 + 8;
            if (gr0 < NN)
                *(uint32_t*)&Y[(size_t)gr0 * ldy + col] = pack_bf2(make_float2(v0, v1));
            else { v0 = 0.f; v1 = 0.f; }
            if (gr1 < NN)
                *(uint32_t*)&Y[(size_t)gr1 * ldy + col] = pack_bf2(make_float2(v2, v3));
            else { v2 = 0.f; v3 = 0.f; }
            sA[nt] += v0 + v2;
            sB[nt] += v1 + v3;
            qA[nt] = fmaf(v0, v0, fmaf(v2, v2, qA[nt]));
            qB[nt] = fmaf(v1, v1, fmaf(v3, v3, qB[nt]));
        }
        p ^= 1;
    }

#pragma unroll
    for (int nt = 0; nt < 16; nt++) {
        float s0 = sA[nt], s1 = sB[nt], q0 = qA[nt], q1 = qB[nt];
#pragma unroll
        for (int h = 4; h < 32; h <<= 1) {
            s0 += __shfl_xor_sync(0xffffffffu, s0, h);
            s1 += __shfl_xor_sync(0xffffffffu, s1, h);
            q0 += __shfl_xor_sync(0xffffffffu, q0, h);
            q1 += __shfl_xor_sync(0xffffffffu, q1, h);
        }
        if (lane < 4) {
            int col = nt * 8 + 2 * lane;
            atomicAdd(&sstat[col], s0);
            atomicAdd(&sstat[col + 1], s1);
            atomicAdd(&sstat[128 + col], q0);
            atomicAdd(&sstat[128 + col + 1], q1);
        }
    }
    __syncthreads();
    atomicAdd(&stats_out[tid], sstat[tid]);
}

// ---------------- CSR scan (deg re-zeroed here for the next replay) ----------------
__global__ void scan1_kernel() {
    __shared__ int wsum[32];
    int t = threadIdx.x, lane = t & 31, w = t >> 5;
    int idx = blockIdx.x * 1024 + t;
    int v = 0;
    if (idx < NN) {
        v = d_deg[idx];
        d_deg[idx] = 0;
    }
    int x = v;
#pragma unroll
    for (int d = 1; d < 32; d <<= 1) {
        int y = __shfl_up_sync(0xffffffffu, x, d);
        if (lane >= d) x += y;
    }
    if (lane == 31) wsum[w] = x;
    __syncthreads();
    if (w == 0) {
        int s = wsum[lane];
#pragma unroll
        for (int d = 1; d < 32; d <<= 1) {
            int y = __shfl_up_sync(0xffffffffu, s, d);
            if (lane >= d) s += y;
        }
        wsum[lane] = s;
    }
    __syncthreads();
    int woff = (w > 0) ? wsum[w - 1] : 0;
    int excl = woff + x - v;
    if (idx < NN) d_off[idx] = excl;
    if (t == 1023) d_bsum[blockIdx.x] = woff + x;
}

__global__ void scan2_kernel() {
    __shared__ int bs[SCAN_NB];
    __shared__ int boff_s;
    int t = threadIdx.x;
    if (t < SCAN_NB) bs[t] = d_bsum[t];
    __syncthreads();
    if (t == 0) {
        int acc = 0;
#pragma unroll 1
        for (int b = 0; b < (int)blockIdx.x; b++) acc += bs[b];
        boff_s = acc;
        if (blockIdx.x == SCAN_NB - 1) {
            int tot = acc;
            for (int b = blockIdx.x; b < SCAN_NB; b++) tot += bs[b];
            d_off[NN] = tot;
        }
    }
    __syncthreads();
    int boff = boff_s;
    int idx = blockIdx.x * 1024 + t;
    if (idx < NN) {
        int val = d_off[idx] + boff;
        d_off[idx] = val;
        d_cursor[idx] = val;
    }
}

__global__ void fill_kernel(const int* __restrict__ src, const int* __restrict__ dst) {
    int i = blockIdx.x * blockDim.x + threadIdx.x;
    if (i < EE) {
        int p = atomicAdd(&d_cursor[dst[i]], 1);
        d_csr[p] = src[i];
    }
}

// ---------------- pooling offsets (both levels in one launch) ----------------
__global__ void offsets_kernel(const int* __restrict__ n2s, const int* __restrict__ s2g) {
    int i = blockIdx.x * blockDim.x + threadIdx.x;
    if (i <= SS) {
        int lo = 0, hi = NN;
        while (lo < hi) {
            int mid = (lo + hi) >> 1;
            if (n2s[mid] < i) lo = mid + 1; else hi = mid;
        }
        d_suboff[i] = lo;
    }
    int g = i - (SS + 1);
    if (g >= 0 && g <= GG) {
        int lo = 0, hi = SS;
        while (lo < hi) {
            int mid = (lo + hi) >> 1;
            if (s2g[mid] < g) lo = mid + 1; else hi = mid;
        }
        d_gphoff[g] = lo;
    }
}

__global__ void segmean1_kernel(const __nv_bfloat16* __restrict__ in, const int* __restrict__ off,
                                float* __restrict__ out,
                                const float* __restrict__ statsA,
                                const float* __restrict__ g2, const float* __restrict__ be2) {
    int s = blockIdx.x, t = threadIdx.x;
    int lt = t >> 5;
    int c0 = (t & 31) * 4;
    const float* st = statsA + (size_t)(2 * lt + 1) * 256;
    float4 sc4, sh4;
    {
        float sc, sh;
        bn_from_stats(st, g2 + lt * HH, be2 + lt * HH, c0 + 0, sc, sh); sc4.x = sc; sh4.x = sh;
        bn_from_stats(st, g2 + lt * HH, be2 + lt * HH, c0 + 1, sc, sh); sc4.y = sc; sh4.y = sh;
        bn_from_stats(st, g2 + lt * HH, be2 + lt * HH, c0 + 2, sc, sh); sc4.z = sc; sh4.z = sh;
        bn_from_stats(st, g2 + lt * HH, be2 + lt * HH, c0 + 3, sc, sh); sc4.w = sc; sh4.w = sh;
    }
    int r0 = off[s], r1 = off[s + 1];
    float4 acc = make_float4(0.f, 0.f, 0.f, 0.f);
    for (int r = r0; r < r1; r++) {
        float4 v = bf4_to_f4(*(const uint2*)&in[(size_t)r * (LL * HH) + t * 4]);
        v = act4(v, sc4, sh4);
        acc.x += v.x; acc.y += v.y; acc.z += v.z; acc.w += v.w;
    }
    float inv = 1.0f / fmaxf((float)(r1 - r0), 1.0f);
    float4 o = make_float4(acc.x * inv, acc.y * inv, acc.z * inv, acc.w * inv);
    *(float4*)&out[(size_t)s * (LL * HH) + t * 4] = o;
}

// ---------------- fused graph-mean + head ----------------
__global__ void head_kernel(const float* __restrict__ sub, const int* __restrict__ goff,
                            const float* __restrict__ w1, const float* __restrict__ bb1,
                            const float* __restrict__ w2, const float* __restrict__ bb2,
                            float* __restrict__ out) {
    __shared__ float grow[LL * HH];
    __shared__ float hbuf[HH];
    __shared__ float obuf[CC];
    int g = blockIdx.x, t = threadIdx.x;
    {
        int r0 = goff[g], r1 = goff[g + 1];
        float4 acc = make_float4(0.f, 0.f, 0.f, 0.f);
        for (int r = r0; r < r1; r++) {
            float4 v = *(const float4*)&sub[(size_t)r * (LL * HH) + t * 4];
            acc.x += v.x; acc.y += v.y; acc.z += v.z; acc.w += v.w;
        }
        float inv = 1.0f / fmaxf((float)(r1 - r0), 1.0f);
        *(float4*)&grow[t * 4] = make_float4(acc.x * inv, acc.y * inv, acc.z * inv, acc.w * inv);
    }
    __syncthreads();
    float acc = bb1[t];
#pragma unroll 8
    for (int k = 0; k < LL * HH; k++) acc = fmaf(grow[k], w1[(size_t)t * (LL * HH) + k], acc);
    hbuf[t] = fmaxf(acc, 0.f);
    __syncthreads();
    if (t < CC) {
        float a = bb2[t];
#pragma unroll 8
        for (int k = 0; k < HH; k++) a = fmaf(hbuf[k], w2[t * HH + k], a);
        obuf[t] = a;
    }
    __syncthreads();
    if (t == 0) {
        float m = obuf[0];
#pragma unroll
        for (int j = 1; j < CC; j++) m = fmaxf(m, obuf[j]);
        float se = 0.f;
#pragma unroll
        for (int j = 0; j < CC; j++) se += expf(obuf[j] - m);
        float lse = m + logf(se);
#pragma unroll
        for (int j = 0; j < CC; j++) out[g * CC + j] = obuf[j] - lse;
    }
}

// ---------------- launcher ----------------
extern "C" void kernel_launch(void* const* d_in, const int* in_sizes, int n_in,
                              void* d_out, int out_size) {
    const float* x     = (const float*)d_in[0];
    const int*   ei    = (const int*)d_in[1];
    const int*   n2s   = (const int*)d_in[2];
    const int*   s2g   = (const int*)d_in[3];
    const float* W1    = (const float*)d_in[4];
    const float* b1    = (const float*)d_in[5];
    const float* g1    = (const float*)d_in[6];
    const float* be1   = (const float*)d_in[7];
    const float* W2    = (const float*)d_in[8];
    const float* b2    = (const float*)d_in[9];
    const float* g2    = (const float*)d_in[10];
    const float* be2   = (const float*)d_in[11];
    const float* eps   = (const float*)d_in[12];
    const float* lin1W = (const float*)d_in[13];
    const float* lin1b = (const float*)d_in[14];
    const float* lin2W = (const float*)d_in[15];
    const float* lin2b = (const float*)d_in[16];
    float* out = (float*)d_out;

    void* p;
    cudaGetSymbolAddress(&p, d_ubf);    __nv_bfloat16* ubfp   = (__nv_bfloat16*)p;
    cudaGetSymbolAddress(&p, d_tbf);    __nv_bfloat16* tbfp   = (__nv_bfloat16*)p;
    cudaGetSymbolAddress(&p, d_xbf);    __nv_bfloat16* xbfp   = (__nv_bfloat16*)p;
    cudaGetSymbolAddress(&p, d_abf);    __nv_bfloat16* abfp   = (__nv_bfloat16*)p;
    cudaGetSymbolAddress(&p, d_featbf); __nv_bfloat16* featp  = (__nv_bfloat16*)p;
    cudaGetSymbolAddress(&p, d_statsA); float* statsp  = (float*)p;
    cudaGetSymbolAddress(&p, d_sub);    float* subp    = (float*)p;
    cudaGetSymbolAddress(&p, d_suboff); int* suboffp   = (int*)p;
    cudaGetSymbolAddress(&p, d_gphoff); int* gphoffp   = (int*)p;
    cudaGetSymbolAddress(&p, d_Wbf);    __nv_bfloat16* wbfp = (__nv_bfloat16*)p;

    cudaFuncSetAttribute((const void*)mm_hmma_kernel<false>,
                         cudaFuncAttributeMaxDynamicSharedMemorySize, MM_SMEM);
    cudaFuncSetAttribute((const void*)mm_hmma_kernel<true>,
                         cudaFuncAttributeMaxDynamicSharedMemorySize, MM_SMEM);

    const int* src = ei;
    const int* dst = ei + EE;

    init_kernel<<<(NN * 32 + 255) / 256, 256>>>(x, W1, W2, dst);
    scan1_kernel<<<SCAN_NB, 1024>>>();
    scan2_kernel<<<SCAN_NB, 1024>>>();
    fill_kernel<<<(EE + 255) / 256, 256>>>(src, dst);

    const int agg_blocks = (NN + 15) / 16;
    for (int l = 0; l < LL; l++) {
        const __nv_bfloat16* w1bf = wbfp + (size_t)(l * 2) * 16384;
        const __nv_bfloat16* w2bf = wbfp + (size_t)(l * 2 + 1) * 16384;
        float* st1 = statsp + (size_t)(2 * l) * 256;
        float* st2 = statsp + (size_t)(2 * l + 1) * 256;

        const __nv_bfloat16* agg_in = xbfp;
        if (l > 0) {
            act_kernel<<<1184, 256>>>(
                featp + (size_t)(l - 1) * HH,
                statsp + (size_t)(2 * (l - 1) + 1) * 256,
                g2 + (size_t)(l - 1) * HH, be2 + (size_t)(l - 1) * HH, abfp);
            agg_in = abfp;
        }
        agg_kernel<<<agg_blocks, 256>>>(agg_in, eps, l, ubfp);

        mm_hmma_kernel<false><<<MMGRID, 256, MM_SMEM>>>(
            ubfp, HH, nullptr, nullptr, nullptr, w1bf,
            b1 + (size_t)l * HH, st1, tbfp, HH);

        mm_hmma_kernel<true><<<MMGRID, 256, MM_SMEM>>>(
            tbfp, HH, st1, g1 + (size_t)l * HH, be1 + (size_t)l * HH,
            w2bf, b2 + (size_t)l * HH, st2,
            featp + (size_t)l * HH, LL * HH);
    }

    offsets_kernel<<<(SS + GG + 2 + 255) / 256, 256>>>(n2s, s2g);
    segmean1_kernel<<<SS, 128>>>(featp, suboffp, subp, statsp, g2, be2);
    head_kernel<<<GG, 128>>>(subp, gphoffp, lin1W, lin1b, lin2W, lin2b, out);
}

// round 17
// speedup vs baseline: 1.2744x; 1.0009x over previous
#include <cuda_runtime.h>
#include <cuda_bf16.h>
#include <cstdint>
#include <cstddef>

#define NN 100000
#define EE 1600000
#define FF 128
#define HH 128
#define LL 4
#define SS 10000
#define GG 256
#define CC 10
#define SCAN_NB 98
#define NTILES 782
#define MMGRID 148

// ---------------- scratch (device globals; no allocation allowed) ----------------
__device__ int   d_deg[NN];          // zero at module load; re-zeroed in scan1 each run
__device__ int   d_off[NN + 1];
__device__ int   d_cursor[NN];
__device__ int   d_csr[EE];
__device__ int   d_bsum[SCAN_NB];
__device__ __nv_bfloat16 d_ubf[(size_t)NN * HH];
__device__ __nv_bfloat16 d_tbf[(size_t)NN * HH];
__device__ __nv_bfloat16 d_xbf[(size_t)NN * FF];
__device__ __nv_bfloat16 d_abf[(size_t)NN * HH];   // pre-activated act(feat[l-1]) (compact)
__device__ __nv_bfloat16 d_featbf[(size_t)NN * LL * HH];
__device__ float d_statsA[8 * 256];
__device__ int   d_suboff[SS + 1];
__device__ int   d_gphoff[GG + 1];
__device__ float d_sub[(size_t)SS * LL * HH];
__device__ __nv_bfloat16 d_Wbf[8 * 128 * 128];

// ---------------- smem layout for persistent mm kernel ----------------
#define SM_BIAS  0
#define SM_SSC   512
#define SM_SSH   1024
#define SM_STATS 1536
#define SM_WH    2560
#define SM_STG0  (SM_WH + 34816)      // 37376
#define STGB     34816                // 128 rows * 272B (bf16 stage)
#define SM_STG1  (SM_STG0 + STGB)     // 72192
#define MM_SMEM  (SM_STG1 + STGB)     // 107008

__device__ __forceinline__ uint32_t smem_u32(const void* p) {
    uint32_t a;
    asm("{ .reg .u64 t; cvta.to.shared.u64 t, %1; cvt.u32.u64 %0, t; }" : "=r"(a) : "l"(p));
    return a;
}
__device__ __forceinline__ void ldsm_x2(uint32_t* b, uint32_t addr) {
    asm volatile("ldmatrix.sync.aligned.m8n8.x2.shared.b16 {%0,%1}, [%2];"
        : "=r"(b[0]), "=r"(b[1]) : "r"(addr));
}
__device__ __forceinline__ void mma_bf16(float* c, const uint32_t* a, const uint32_t* b) {
    asm volatile("mma.sync.aligned.m16n8k16.row.col.f32.bf16.bf16.f32 "
        "{%0,%1,%2,%3}, {%4,%5,%6,%7}, {%8,%9}, {%0,%1,%2,%3};"
        : "+f"(c[0]), "+f"(c[1]), "+f"(c[2]), "+f"(c[3])
        : "r"(a[0]), "r"(a[1]), "r"(a[2]), "r"(a[3]), "r"(b[0]), "r"(b[1]));
}
__device__ __forceinline__ void cpasync16(uint32_t dst, const void* src, int sz) {
    asm volatile("cp.async.ca.shared.global [%0], [%1], 16, %2;"
        :: "r"(dst), "l"(src), "r"(sz) : "memory");
}
#define CP_COMMIT() asm volatile("cp.async.commit_group;" ::: "memory")
#define CP_WAIT0()  asm volatile("cp.async.wait_group 0;" ::: "memory")

__device__ __forceinline__ uint32_t pack_bf2(float2 v) {
    __nv_bfloat162 h = __floats2bfloat162_rn(v.x, v.y);
    return *reinterpret_cast<uint32_t*>(&h);
}
__device__ __forceinline__ float2 unpack_bf2(uint32_t w) {
    return make_float2(__uint_as_float(w << 16), __uint_as_float(w & 0xFFFF0000u));
}
__device__ __forceinline__ float4 bf4_to_f4(uint2 w) {
    float2 f0 = unpack_bf2(w.x);
    float2 f1 = unpack_bf2(w.y);
    return make_float4(f0.x, f0.y, f1.x, f1.y);
}
__device__ __forceinline__ uint32_t act_bf2(uint32_t w, float2 sc, float2 sh) {
    float2 v = unpack_bf2(w);
    v.x = fmaxf(fmaf(v.x, sc.x, sh.x), 0.f);
    v.y = fmaxf(fmaf(v.y, sc.y, sh.y), 0.f);
    return pack_bf2(v);
}

__device__ __forceinline__ float4 act4(float4 v, float4 sc, float4 sh) {
    v.x = fmaxf(fmaf(v.x, sc.x, sh.x), 0.f);
    v.y = fmaxf(fmaf(v.y, sc.y, sh.y), 0.f);
    v.z = fmaxf(fmaf(v.z, sc.z, sh.z), 0.f);
    v.w = fmaxf(fmaf(v.w, sc.w, sh.w), 0.f);
    return v;
}

__device__ __forceinline__ void bn_from_stats(const float* st, const float* gamma,
                                              const float* beta, int c,
                                              float& sc, float& sh) {
    const float inv_n = 1.0f / (float)NN;
    float mu = st[c] * inv_n;
    float var = fmaf(-mu, mu, st[HH + c] * inv_n);
    float rinv = rsqrtf(var + 1e-5f);
    sc = rinv * gamma[c];
    sh = fmaf(-mu, sc, beta[c]);
}

__device__ __forceinline__ void mm_issue_copy(const __nv_bfloat16* __restrict__ Ain, int lda,
                                              uint32_t sb, int tile, int buf, int tid) {
    uint32_t base = sb + SM_STG0 + (uint32_t)buf * STGB;
    int row0 = tile * 128;
#pragma unroll
    for (int j = 0; j < 8; j++) {
        int c = tid + 256 * j;
        int r = c >> 4, ch = c & 15;
        int gr = row0 + r;
        uint32_t dst = base + (uint32_t)(r * 272 + ch * 16);
        int ok = (gr < NN) ? 16 : 0;
        const __nv_bfloat16* src = Ain + (size_t)(gr < NN ? gr : 0) * lda + ch * 8;
        cpasync16(dst, src, ok);
    }
}

// ---------------- init: x->bf16 + W->bf16 + zero stats + edge count (deg pre-zeroed) ----------------
__global__ void init_kernel(const float* __restrict__ x,
                            const float* __restrict__ W1, const float* __restrict__ W2,
                            const int* __restrict__ dst) {
    int i = blockIdx.x * blockDim.x + threadIdx.x;
    if (i < NN * 32) {
        float4 v = *(const float4*)&x[(size_t)i * 4];
        uint2 o;
        o.x = pack_bf2(make_float2(v.x, v.y));
        o.y = pack_bf2(make_float2(v.z, v.w));
        *(uint2*)&d_xbf[(size_t)i * 4] = o;
    }
    if (i < 8 * 256) d_statsA[i] = 0.f;
    if (i < 8 * 16384) {
        int mat = i >> 14, e = i & 16383, l = mat >> 1;
        float v = (mat & 1) ? W2[(size_t)l * 16384 + e] : W1[(size_t)l * 16384 + e];
        d_Wbf[i] = __float2bfloat16(v);
    }
    if (i < EE) atomicAdd(&d_deg[dst[i]], 1);
}

// ---------------- act pass: d_abf = BN+ReLU(feat slot) (compact [NN,128] bf16) ----------------
__global__ void act_kernel(const __nv_bfloat16* __restrict__ in,
                           const float* __restrict__ st,
                           const float* __restrict__ gamma, const float* __restrict__ beta,
                           __nv_bfloat16* __restrict__ outp) {
    __shared__ float ssc[HH], ssh[HH];
    int tid = threadIdx.x;
    if (tid < HH) bn_from_stats(st, gamma, beta, tid, ssc[tid], ssh[tid]);
    __syncthreads();
    int stride = gridDim.x * blockDim.x;
#pragma unroll 1
    for (int i = blockIdx.x * blockDim.x + tid; i < NN * 32; i += stride) {
        int r = i >> 5, cp = i & 31;
        uint2 w = *(const uint2*)&in[(size_t)r * (LL * HH) + cp * 4];
        float2 s0 = *(const float2*)&ssc[cp * 4],     h0 = *(const float2*)&ssh[cp * 4];
        float2 s1 = *(const float2*)&ssc[cp * 4 + 2], h1 = *(const float2*)&ssh[cp * 4 + 2];
        uint2 o;
        o.x = act_bf2(w.x, s0, h0);
        o.y = act_bf2(w.y, s1, h1);
        *(uint2*)&outp[(size_t)r * HH + cp * 4] = o;
    }
}

// ---------------- aggregation: 2 nodes/warp, 16B/lane gathers, HADD2 batch accumulation ----------------
__global__ void agg_kernel(const __nv_bfloat16* __restrict__ xin,   // [NN,128] bf16, pre-activated
                           const float* __restrict__ eps_ptr, int layer,
                           __nv_bfloat16* __restrict__ u) {
    int tid = threadIdx.x;
    int wid = tid >> 5, lane = tid & 31;
    int half = lane >> 4, hl = lane & 15;
    int node = blockIdx.x * 16 + wid * 2 + half;
    if (node >= NN) return;
    float e = 1.0f + eps_ptr[layer];
    int c0 = hl * 8;
    int s = d_off[node], epos = d_off[node + 1];
    float acc[8];
#pragma unroll
    for (int q = 0; q < 8; q++) acc[q] = 0.f;

    int j = s;
    if (j + 8 <= epos) {
        int ii[8];
#pragma unroll
        for (int q = 0; q < 8; q++) ii[q] = d_csr[j + q];
#pragma unroll 1
        while (true) {
            uint4 w[8];
#pragma unroll
            for (int q = 0; q < 8; q++)
                w[q] = *(const uint4*)&xin[(size_t)ii[q] * HH + c0];
            int nj = j + 8;
            bool more = (nj + 8 <= epos);
            if (more) {
#pragma unroll
                for (int q = 0; q < 8; q++) ii[q] = d_csr[nj + q];
            }
            // bf16x2 in-batch accumulation (HADD2), fp32 flush per batch
            __nv_bfloat162 bacc[4];
#pragma unroll
            for (int k = 0; k < 4; k++) bacc[k] = __nv_bfloat162(__nv_bfloat16(0.f), __nv_bfloat16(0.f));
#pragma unroll
            for (int q = 0; q < 8; q++) {
                const uint32_t* ww = (const uint32_t*)&w[q];
#pragma unroll
                for (int k = 0; k < 4; k++)
                    bacc[k] = __hadd2(bacc[k], *reinterpret_cast<const __nv_bfloat162*>(&ww[k]));
            }
#pragma unroll
            for (int k = 0; k < 4; k++) {
                float2 v = __bfloat1622float2(bacc[k]);
                acc[2 * k] += v.x;
                acc[2 * k + 1] += v.y;
            }
            j = nj;
            if (!more) break;
        }
    }
#pragma unroll 1
    for (; j < epos; ++j) {
        int i0 = d_csr[j];
        uint4 w0 = *(const uint4*)&xin[(size_t)i0 * HH + c0];
        const uint32_t* ww = (const uint32_t*)&w0;
#pragma unroll
        for (int k = 0; k < 4; k++) {
            float2 v = unpack_bf2(ww[k]);
            acc[2 * k] += v.x;
            acc[2 * k + 1] += v.y;
        }
    }
    // self term
    {
        uint4 w0 = *(const uint4*)&xin[(size_t)node * HH + c0];
        const uint32_t* ww = (const uint32_t*)&w0;
#pragma unroll
        for (int k = 0; k < 4; k++) {
            float2 v = unpack_bf2(ww[k]);
            acc[2 * k] = fmaf(e, v.x, acc[2 * k]);
            acc[2 * k + 1] = fmaf(e, v.y, acc[2 * k + 1]);
        }
    }
    uint4 o;
    uint32_t* oo = (uint32_t*)&o;
#pragma unroll
    for (int k = 0; k < 4; k++)
        oo[k] = pack_bf2(make_float2(acc[2 * k], acc[2 * k + 1]));
    *(uint4*)&u[(size_t)node * HH + c0] = o;
}

// ---------------- persistent pipelined GEMM (R11/R14 structure, verbatim) ----------------
template <bool HAS_T>
__global__ void __launch_bounds__(256, 1)
mm_hmma_kernel(const __nv_bfloat16* __restrict__ Ain, int lda,
               const float* __restrict__ stats_in,
               const float* __restrict__ gamma, const float* __restrict__ beta,
               const __nv_bfloat16* __restrict__ Wbf,
               const float* __restrict__ bias,
               float* __restrict__ stats_out,
               __nv_bfloat16* __restrict__ Y, int ldy) {
    extern __shared__ char smem[];
    uint32_t sb = smem_u32(smem);
    int tid = threadIdx.x, wid = tid >> 5, lane = tid & 31;
    int gid = lane >> 2, ctib = lane & 3;
    float* sbias = (float*)(smem + SM_BIAS);
    float* ssc   = (float*)(smem + SM_SSC);
    float* ssh   = (float*)(smem + SM_SSH);
    float* sstat = (float*)(smem + SM_STATS);

    if (tid < 128) {
        sbias[tid] = bias[tid];
        if (HAS_T) bn_from_stats(stats_in, gamma, beta, tid, ssc[tid], ssh[tid]);
    }
    sstat[tid] = 0.f;

#pragma unroll
    for (int i = tid; i < 128 * 16; i += 256) {
        int r = i >> 4, c8 = (i & 15) * 8;
        uint32_t dsto = (uint32_t)(r * 272 + c8 * 2);
        *(uint4*)(smem + SM_WH + dsto) = *(const uint4*)&Wbf[r * 128 + c8];
    }

    mm_issue_copy(Ain, lda, sb, blockIdx.x, 0, tid);
    CP_COMMIT();

    float sA[16], sB[16], qA[16], qB[16];
#pragma unroll
    for (int nt = 0; nt < 16; nt++) { sA[nt] = 0.f; sB[nt] = 0.f; qA[nt] = 0.f; qB[nt] = 0.f; }

    int p = 0;
    int r0w = 16 * wid + gid;
#pragma unroll 1
    for (int tile = blockIdx.x; tile < NTILES; tile += MMGRID) {
        CP_WAIT0();
        __syncthreads();

        const char* stg = smem + SM_STG0 + (uint32_t)p * STGB;
        uint32_t ah[32];
#pragma unroll
        for (int k8 = 0; k8 < 8; k8++) {
            uint32_t co = (uint32_t)(k8 * 32 + ctib * 4);
            uint32_t w00 = *(const uint32_t*)(stg + r0w * 272 + co);
            uint32_t w10 = *(const uint32_t*)(stg + (r0w + 8) * 272 + co);
            uint32_t w01 = *(const uint32_t*)(stg + r0w * 272 + co + 16);
            uint32_t w11 = *(const uint32_t*)(stg + (r0w + 8) * 272 + co + 16);
            if (HAS_T) {
                int cc = k8 * 16 + 2 * ctib;
                float2 sa = *(const float2*)&ssc[cc],     ha = *(const float2*)&ssh[cc];
                float2 sc = *(const float2*)&ssc[cc + 8], hc = *(const float2*)&ssh[cc + 8];
                w00 = act_bf2(w00, sa, ha);
                w10 = act_bf2(w10, sa, ha);
                w01 = act_bf2(w01, sc, hc);
                w11 = act_bf2(w11, sc, hc);
            }
            ah[k8 * 4 + 0] = w00;
            ah[k8 * 4 + 1] = w10;
            ah[k8 * 4 + 2] = w01;
            ah[k8 * 4 + 3] = w11;
        }
        __syncthreads();

        int nxt = tile + MMGRID;
        if (nxt < NTILES) mm_issue_copy(Ain, lda, sb, nxt, 1 - p, tid);
        CP_COMMIT();

        int row0 = tile * 128;
        int g = lane & 7, q = (lane >> 3) & 1;
        uint32_t wbase = sb + SM_WH + (uint32_t)(g * 272 + q * 16);
#pragma unroll
        for (int nt = 0; nt < 16; nt++) {
            float ca[4] = {0.f, 0.f, 0.f, 0.f};
            float cb[4] = {0.f, 0.f, 0.f, 0.f};
#pragma unroll
            for (int k8 = 0; k8 < 4; k8++) {
                uint32_t wa = wbase + (uint32_t)(nt * 8 * 272 + k8 * 32);
                uint32_t bh[2], bh2[2];
                ldsm_x2(bh, wa);
                ldsm_x2(bh2, wa + 4 * 32);
                mma_bf16(ca, &ah[k8 * 4], bh);
                mma_bf16(cb, &ah[(k8 + 4) * 4], bh2);
            }
            int col = nt * 8 + 2 * ctib;
            float bx = sbias[col], by = sbias[col + 1];
            float v0 = ca[0] + cb[0] + bx;
            float v1 = ca[1] + cb[1] + by;
            float v2 = ca[2] + cb[2] + bx;
            float v3 = ca[3] + cb[3] + by;
            int gr0 = row0 + r0w, gr1 = gr0 + 8;
            if (gr0 < NN)
                *(uint32_t*)&Y[(size_t)gr0 * ldy + col] = pack_bf2(make_float2(v0, v1));
            else { v0 = 0.f; v1 = 0.f; }
            if (gr1 < NN)
                *(uint32_t*)&Y[(size_t)gr1 * ldy + col] = pack_bf2(make_float2(v2, v3));
            else { v2 = 0.f; v3 = 0.f; }
            sA[nt] += v0 + v2;
            sB[nt] += v1 + v3;
            qA[nt] = fmaf(v0, v0, fmaf(v2, v2, qA[nt]));
            qB[nt] = fmaf(v1, v1, fmaf(v3, v3, qB[nt]));
        }
        p ^= 1;
    }

#pragma unroll
    for (int nt = 0; nt < 16; nt++) {
        float s0 = sA[nt], s1 = sB[nt], q0 = qA[nt], q1 = qB[nt];
#pragma unroll
        for (int h = 4; h < 32; h <<= 1) {
            s0 += __shfl_xor_sync(0xffffffffu, s0, h);
            s1 += __shfl_xor_sync(0xffffffffu, s1, h);
            q0 += __shfl_xor_sync(0xffffffffu, q0, h);
            q1 += __shfl_xor_sync(0xffffffffu, q1, h);
        }
        if (lane < 4) {
            int col = nt * 8 + 2 * lane;
            atomicAdd(&sstat[col], s0);
            atomicAdd(&sstat[col + 1], s1);
            atomicAdd(&sstat[128 + col], q0);
            atomicAdd(&sstat[128 + col + 1], q1);
        }
    }
    __syncthreads();
    atomicAdd(&stats_out[tid], sstat[tid]);
}

// ---------------- CSR scan (deg re-zeroed here for the next replay) ----------------
__global__ void scan1_kernel() {
    __shared__ int wsum[32];
    int t = threadIdx.x, lane = t & 31, w = t >> 5;
    int idx = blockIdx.x * 1024 + t;
    int v = 0;
    if (idx < NN) {
        v = d_deg[idx];
        d_deg[idx] = 0;
    }
    int x = v;
#pragma unroll
    for (int d = 1; d < 32; d <<= 1) {
        int y = __shfl_up_sync(0xffffffffu, x, d);
        if (lane >= d) x += y;
    }
    if (lane == 31) wsum[w] = x;
    __syncthreads();
    if (w == 0) {
        int s = wsum[lane];
#pragma unroll
        for (int d = 1; d < 32; d <<= 1) {
            int y = __shfl_up_sync(0xffffffffu, s, d);
            if (lane >= d) s += y;
        }
        wsum[lane] = s;
    }
    __syncthreads();
    int woff = (w > 0) ? wsum[w - 1] : 0;
    int excl = woff + x - v;
    if (idx < NN) d_off[idx] = excl;
    if (t == 1023) d_bsum[blockIdx.x] = woff + x;
}

__global__ void scan2_kernel() {
    __shared__ int bs[SCAN_NB];
    __shared__ int boff_s;
    int t = threadIdx.x;
    if (t < SCAN_NB) bs[t] = d_bsum[t];
    __syncthreads();
    if (t == 0) {
        int acc = 0;
#pragma unroll 1
        for (int b = 0; b < (int)blockIdx.x; b++) acc += bs[b];
        boff_s = acc;
        if (blockIdx.x == SCAN_NB - 1) {
            int tot = acc;
            for (int b = blockIdx.x; b < SCAN_NB; b++) tot += bs[b];
            d_off[NN] = tot;
        }
    }
    __syncthreads();
    int boff = boff_s;
    int idx = blockIdx.x * 1024 + t;
    if (idx < NN) {
        int val = d_off[idx] + boff;
        d_off[idx] = val;
        d_cursor[idx] = val;
    }
}

__global__ void fill_kernel(const int* __restrict__ src, const int* __restrict__ dst) {
    int i = blockIdx.x * blockDim.x + threadIdx.x;
    if (i < EE) {
        int p = atomicAdd(&d_cursor[dst[i]], 1);
        d_csr[p] = src[i];
    }
}

// ---------------- pooling offsets (both levels in one launch) ----------------
__global__ void offsets_kernel(const int* __restrict__ n2s, const int* __restrict__ s2g) {
    int i = blockIdx.x * blockDim.x + threadIdx.x;
    if (i <= SS) {
        int lo = 0, hi = NN;
        while (lo < hi) {
            int mid = (lo + hi) >> 1;
            if (n2s[mid] < i) lo = mid + 1; else hi = mid;
        }
        d_suboff[i] = lo;
    }
    int g = i - (SS + 1);
    if (g >= 0 && g <= GG) {
        int lo = 0, hi = SS;
        while (lo < hi) {
            int mid = (lo + hi) >> 1;
            if (s2g[mid] < g) lo = mid + 1; else hi = mid;
        }
        d_gphoff[g] = lo;
    }
}

__global__ void segmean1_kernel(const __nv_bfloat16* __restrict__ in, const int* __restrict__ off,
                                float* __restrict__ out,
                                const float* __restrict__ statsA,
                                const float* __restrict__ g2, const float* __restrict__ be2) {
    int s = blockIdx.x, t = threadIdx.x;
    int lt = t >> 5;
    int c0 = (t & 31) * 4;
    const float* st = statsA + (size_t)(2 * lt + 1) * 256;
    float4 sc4, sh4;
    {
        float sc, sh;
        bn_from_stats(st, g2 + lt * HH, be2 + lt * HH, c0 + 0, sc, sh); sc4.x = sc; sh4.x = sh;
        bn_from_stats(st, g2 + lt * HH, be2 + lt * HH, c0 + 1, sc, sh); sc4.y = sc; sh4.y = sh;
        bn_from_stats(st, g2 + lt * HH, be2 + lt * HH, c0 + 2, sc, sh); sc4.z = sc; sh4.z = sh;
        bn_from_stats(st, g2 + lt * HH, be2 + lt * HH, c0 + 3, sc, sh); sc4.w = sc; sh4.w = sh;
    }
    int r0 = off[s], r1 = off[s + 1];
    float4 acc = make_float4(0.f, 0.f, 0.f, 0.f);
    for (int r = r0; r < r1; r++) {
        float4 v = bf4_to_f4(*(const uint2*)&in[(size_t)r * (LL * HH) + t * 4]);
        v = act4(v, sc4, sh4);
        acc.x += v.x; acc.y += v.y; acc.z += v.z; acc.w += v.w;
    }
    float inv = 1.0f / fmaxf((float)(r1 - r0), 1.0f);
    float4 o = make_float4(acc.x * inv, acc.y * inv, acc.z * inv, acc.w * inv);
    *(float4*)&out[(size_t)s * (LL * HH) + t * 4] = o;
}

// ---------------- fused graph-mean + head ----------------
__global__ void head_kernel(const float* __restrict__ sub, const int* __restrict__ goff,
                            const float* __restrict__ w1, const float* __restrict__ bb1,
                            const float* __restrict__ w2, const float* __restrict__ bb2,
                            float* __restrict__ out) {
    __shared__ float grow[LL * HH];
    __shared__ float hbuf[HH];
    __shared__ float obuf[CC];
    int g = blockIdx.x, t = threadIdx.x;
    {
        int r0 = goff[g], r1 = goff[g + 1];
        float4 acc = make_float4(0.f, 0.f, 0.f, 0.f);
        for (int r = r0; r < r1; r++) {
            float4 v = *(const float4*)&sub[(size_t)r * (LL * HH) + t * 4];
            acc.x += v.x; acc.y += v.y; acc.z += v.z; acc.w += v.w;
        }
        float inv = 1.0f / fmaxf((float)(r1 - r0), 1.0f);
        *(float4*)&grow[t * 4] = make_float4(acc.x * inv, acc.y * inv, acc.z * inv, acc.w * inv);
    }
    __syncthreads();
    float acc = bb1[t];
#pragma unroll 8
    for (int k = 0; k < LL * HH; k++) acc = fmaf(grow[k], w1[(size_t)t * (LL * HH) + k], acc);
    hbuf[t] = fmaxf(acc, 0.f);
    __syncthreads();
    if (t < CC) {
        float a = bb2[t];
#pragma unroll 8
        for (int k = 0; k < HH; k++) a = fmaf(hbuf[k], w2[t * HH + k], a);
        obuf[t] = a;
    }
    __syncthreads();
    if (t == 0) {
        float m = obuf[0];
#pragma unroll
        for (int j = 1; j < CC; j++) m = fmaxf(m, obuf[j]);
        float se = 0.f;
#pragma unroll
        for (int j = 0; j < CC; j++) se += expf(obuf[j] - m);
        float lse = m + logf(se);
#pragma unroll
        for (int j = 0; j < CC; j++) out[g * CC + j] = obuf[j] - lse;
    }
}

// ---------------- launcher ----------------
extern "C" void kernel_launch(void* const* d_in, const int* in_sizes, int n_in,
                              void* d_out, int out_size) {
    const float* x     = (const float*)d_in[0];
    const int*   ei    = (const int*)d_in[1];
    const int*   n2s   = (const int*)d_in[2];
    const int*   s2g   = (const int*)d_in[3];
    const float* W1    = (const float*)d_in[4];
    const float* b1    = (const float*)d_in[5];
    const float* g1    = (const float*)d_in[6];
    const float* be1   = (const float*)d_in[7];
    const float* W2    = (const float*)d_in[8];
    const float* b2    = (const float*)d_in[9];
    const float* g2    = (const float*)d_in[10];
    const float* be2   = (const float*)d_in[11];
    const float* eps   = (const float*)d_in[12];
    const float* lin1W = (const float*)d_in[13];
    const float* lin1b = (const float*)d_in[14];
    const float* lin2W = (const float*)d_in[15];
    const float* lin2b = (const float*)d_in[16];
    float* out = (float*)d_out;

    void* p;
    cudaGetSymbolAddress(&p, d_ubf);    __nv_bfloat16* ubfp   = (__nv_bfloat16*)p;
    cudaGetSymbolAddress(&p, d_tbf);    __nv_bfloat16* tbfp   = (__nv_bfloat16*)p;
    cudaGetSymbolAddress(&p, d_xbf);    __nv_bfloat16* xbfp   = (__nv_bfloat16*)p;
    cudaGetSymbolAddress(&p, d_abf);    __nv_bfloat16* abfp   = (__nv_bfloat16*)p;
    cudaGetSymbolAddress(&p, d_featbf); __nv_bfloat16* featp  = (__nv_bfloat16*)p;
    cudaGetSymbolAddress(&p, d_statsA); float* statsp  = (float*)p;
    cudaGetSymbolAddress(&p, d_sub);    float* subp    = (float*)p;
    cudaGetSymbolAddress(&p, d_suboff); int* suboffp   = (int*)p;
    cudaGetSymbolAddress(&p, d_gphoff); int* gphoffp   = (int*)p;
    cudaGetSymbolAddress(&p, d_Wbf);    __nv_bfloat16* wbfp = (__nv_bfloat16*)p;

    cudaFuncSetAttribute((const void*)mm_hmma_kernel<false>,
                         cudaFuncAttributeMaxDynamicSharedMemorySize, MM_SMEM);
    cudaFuncSetAttribute((const void*)mm_hmma_kernel<true>,
                         cudaFuncAttributeMaxDynamicSharedMemorySize, MM_SMEM);

    const int* src = ei;
    const int* dst = ei + EE;

    init_kernel<<<(NN * 32 + 255) / 256, 256>>>(x, W1, W2, dst);
    scan1_kernel<<<SCAN_NB, 1024>>>();
    scan2_kernel<<<SCAN_NB, 1024>>>();
    fill_kernel<<<(EE + 255) / 256, 256>>>(src, dst);

    const int agg_blocks = (NN + 15) / 16;
    for (int l = 0; l < LL; l++) {
        const __nv_bfloat16* w1bf = wbfp + (size_t)(l * 2) * 16384;
        const __nv_bfloat16* w2bf = wbfp + (size_t)(l * 2 + 1) * 16384;
        float* st1 = statsp + (size_t)(2 * l) * 256;
        float* st2 = statsp + (size_t)(2 * l + 1) * 256;

        const __nv_bfloat16* agg_in = xbfp;
        if (l > 0) {
            act_kernel<<<1184, 256>>>(
                featp + (size_t)(l - 1) * HH,
                statsp + (size_t)(2 * (l - 1) + 1) * 256,
                g2 + (size_t)(l - 1) * HH, be2 + (size_t)(l - 1) * HH, abfp);
            agg_in = abfp;
        }
        agg_kernel<<<agg_blocks, 256>>>(agg_in, eps, l, ubfp);

        mm_hmma_kernel<false><<<MMGRID, 256, MM_SMEM>>>(
            ubfp, HH, nullptr, nullptr, nullptr, w1bf,
            b1 + (size_t)l * HH, st1, tbfp, HH);

        mm_hmma_kernel<true><<<MMGRID, 256, MM_SMEM>>>(
            tbfp, HH, st1, g1 + (size_t)l * HH, be1 + (size_t)l * HH,
            w2bf, b2 + (size_t)l * HH, st2,
            featp + (size_t)l * HH, LL * HH);
    }

    offsets_kernel<<<(SS + GG + 2 + 255) / 256, 256>>>(n2s, s2g);
    segmean1_kernel<<<SS, 128>>>(featp, suboffp, subp, statsp, g2, be2);
    head_kernel<<<GG, 128>>>(subp, gphoffp, lin1W, lin1b, lin2W, lin2b, out);
}